// round 10
// baseline (speedup 1.0000x reference)
#include <cuda_runtime.h>
#include <cuda_bf16.h>
#include <cstdint>

#define NN 50000
#define EE 600000
#define DIM 128
#define NCLS 40
#define SCAN_BLK 256
#define SCAN_NB ((NN + SCAN_BLK - 1) / SCAN_BLK)   // 196

// ---------------- scratch (static __device__, no allocation) ----------------
__device__ int   g_cnt[NN];
__device__ int   g_rowptr[NN + 1];
__device__ int   g_fill[NN];
__device__ int   g_srcs[EE];
__device__ int   g_bsum[SCAN_NB];
__device__ int   g_boff[SCAN_NB];
__device__ float g_dinv[NN];
__device__ __align__(16) float g_h1[(size_t)NN * DIM];   // GEMM out (fp32)
__device__ __align__(16) float g_h2[(size_t)NN * DIM];   // layer2 agg out (fp32) for final
__device__ __align__(16) uint32_t g_xhi[(size_t)NN * 64];  // split x (bf16 pairs)
__device__ __align__(16) uint32_t g_xlo[(size_t)NN * 64];
__device__ __align__(16) uint32_t g_hhi[(size_t)NN * 64];  // split agg1 out
__device__ __align__(16) uint32_t g_hlo[(size_t)NN * 64];
__device__ __align__(16) uint32_t g_whi[2 * 8192];         // split W1,W2: [layer][kpair*128+n]
__device__ __align__(16) uint32_t g_wlo[2 * 8192];

__device__ __forceinline__ void split2(float a, unsigned& hi, unsigned& lo, int sh) {
    __nv_bfloat16 hb = __float2bfloat16(a);
    float hf = __bfloat162float(hb);
    __nv_bfloat16 lb = __float2bfloat16(a - hf);
    hi |= (unsigned)__bfloat16_as_ushort(hb) << sh;
    lo |= (unsigned)__bfloat16_as_ushort(lb) << sh;
}

// ---------------- preprocessing ----------------
__global__ void k_zero() {
    int i = blockIdx.x * blockDim.x + threadIdx.x;
    if (i < NN) g_cnt[i] = 0;
}

__global__ void k_hist(const int* __restrict__ col) {
    int i = blockIdx.x * blockDim.x + threadIdx.x;
    if (i < EE) {
        unsigned c = (unsigned)col[i];
        if (c < NN) atomicAdd(&g_cnt[c], 1);
    }
}

__global__ void __launch_bounds__(SCAN_BLK) k_scan1() {
    __shared__ int ws[8];
    int t = threadIdx.x, lane = t & 31, w = t >> 5;
    int i = blockIdx.x * SCAN_BLK + t;
    int v = (i < NN) ? g_cnt[i] : 0;
    if (i < NN) g_dinv[i] = rsqrtf((float)v + 1.0f);
    int incl = v;
    #pragma unroll
    for (int off = 1; off < 32; off <<= 1) {
        int u = __shfl_up_sync(0xffffffffu, incl, off);
        if (lane >= off) incl += u;
    }
    if (lane == 31) ws[w] = incl;
    __syncthreads();
    if (w == 0 && lane < 8) {
        int s = ws[lane];
        #pragma unroll
        for (int off = 1; off < 8; off <<= 1) {
            int u = __shfl_up_sync(0xffu, s, off);
            if (lane >= off) s += u;
        }
        ws[lane] = s;
    }
    __syncthreads();
    int excl = incl - v + (w ? ws[w - 1] : 0);
    if (i < NN) g_rowptr[i] = excl;
    if (t == 0) g_bsum[blockIdx.x] = ws[7];
}

__global__ void __launch_bounds__(SCAN_BLK) k_scan2() {
    __shared__ int ws[8];
    int t = threadIdx.x, lane = t & 31, w = t >> 5;
    int v = (t < SCAN_NB) ? g_bsum[t] : 0;
    int incl = v;
    #pragma unroll
    for (int off = 1; off < 32; off <<= 1) {
        int u = __shfl_up_sync(0xffffffffu, incl, off);
        if (lane >= off) incl += u;
    }
    if (lane == 31) ws[w] = incl;
    __syncthreads();
    if (w == 0 && lane < 8) {
        int s = ws[lane];
        #pragma unroll
        for (int off = 1; off < 8; off <<= 1) {
            int u = __shfl_up_sync(0xffu, s, off);
            if (lane >= off) s += u;
        }
        ws[lane] = s;
    }
    __syncthreads();
    int excl = incl - v + (w ? ws[w - 1] : 0);
    if (t < SCAN_NB) g_boff[t] = excl;
    if (t == SCAN_NB - 1) g_rowptr[NN] = excl + v;
}

__global__ void __launch_bounds__(SCAN_BLK) k_scan3() {
    int i = blockIdx.x * SCAN_BLK + threadIdx.x;
    if (i < NN) {
        int e = g_rowptr[i] + g_boff[blockIdx.x];
        g_rowptr[i] = e;
        g_fill[i] = e;
    }
}

__global__ void k_scatter(const int* __restrict__ row,
                          const int* __restrict__ col) {
    int i = blockIdx.x * blockDim.x + threadIdx.x;
    if (i < EE) {
        unsigned c = (unsigned)col[i];
        unsigned r = (unsigned)row[i];
        if (c < NN && r < NN) {
            int p = atomicAdd(&g_fill[c], 1);
            g_srcs[p] = (int)r;
        }
    }
}

// ---------------- weight / feature splitting ----------------
// g_whi layout: [layer][kpair*128 + n], word = bf16(k=2kp) | bf16(k=2kp+1)<<16
__global__ void k_splitW(const float* __restrict__ W1, const float* __restrict__ W2) {
    int i = blockIdx.x * blockDim.x + threadIdx.x;
    if (i >= 2 * 8192) return;
    const float* W = (i < 8192) ? W1 : W2;
    int j = i & 8191;
    int kp = j >> 7, nn = j & 127;
    float w0 = W[nn * 128 + 2 * kp];
    float w1 = W[nn * 128 + 2 * kp + 1];
    unsigned hi = 0, lo = 0;
    split2(w0, hi, lo, 0);
    split2(w1, hi, lo, 16);
    g_whi[i] = hi;
    g_wlo[i] = lo;
}

// x row-major [node][64 words]
__global__ void k_splitx(const float* __restrict__ x) {
    int i = blockIdx.x * blockDim.x + threadIdx.x;
    if (i >= NN * 64) return;
    float2 v = ((const float2*)x)[i];
    unsigned hi = 0, lo = 0;
    split2(v.x, hi, lo, 0);
    split2(v.y, hi, lo, 16);
    g_xhi[i] = hi;
    g_xlo[i] = lo;
}

// ---------------- mma.sync GEMM: g_h1[n,128] = A[n,128] @ W[128,128]^T ----------------
// split-bf16 3-term: D = Ah@Bh + Ah@Bl + Al@Bh, fp32 accumulate.
// A smem: row-major [64 rows][PADA=69 words]; B smem: kpair-major [64][PADB=136] (conflict-free).
#define PADA 69
#define PADB 136
#define SA_HI 0
#define SA_LO (64 * PADA)                 // 4416
#define SB_HI (2 * 64 * PADA)             // 8832
#define SB_LO (SB_HI + 64 * PADB)         // 17536
#define SMW_TOT (SB_LO + 64 * PADB)       // 26240 words
#define SM_BYTES (SMW_TOT * 4)            // 104960

__device__ __forceinline__ void mma_bf16(float* d, const unsigned* a, unsigned b0, unsigned b1) {
    asm volatile(
        "mma.sync.aligned.m16n8k16.row.col.f32.bf16.bf16.f32 "
        "{%0,%1,%2,%3}, {%4,%5,%6,%7}, {%8,%9}, {%0,%1,%2,%3};"
        : "+f"(d[0]), "+f"(d[1]), "+f"(d[2]), "+f"(d[3])
        : "r"(a[0]), "r"(a[1]), "r"(a[2]), "r"(a[3]), "r"(b0), "r"(b1));
}

__global__ void __launch_bounds__(256, 2)
k_mmagemm(int layer, int n) {
    extern __shared__ __align__(16) uint32_t smw[];
    uint32_t* SAh = smw + SA_HI;
    uint32_t* SAl = smw + SA_LO;
    uint32_t* SBh = smw + SB_HI;
    uint32_t* SBl = smw + SB_LO;
    const uint32_t* Ahi = layer ? g_hhi : g_xhi;
    const uint32_t* Alo = layer ? g_hlo : g_xlo;
    const uint32_t* Whi = g_whi + layer * 8192;
    const uint32_t* Wlo = g_wlo + layer * 8192;
    int t = threadIdx.x, wid = t >> 5, lane = t & 31;
    int row0 = blockIdx.x * 64;

    // A tile copy (64 rows x 32 uint2)
    const uint2* A2h = (const uint2*)Ahi;
    const uint2* A2l = (const uint2*)Alo;
    #pragma unroll
    for (int p = 0; p < 8; p++) {
        int i2 = t + p * 256;
        int r = i2 >> 5, c2 = i2 & 31;
        int gr = row0 + r;
        if (gr >= n) gr = n - 1;
        uint2 vh = A2h[(size_t)gr * 32 + c2];
        uint2 vl = A2l[(size_t)gr * 32 + c2];
        int so = r * PADA + c2 * 2;
        SAh[so] = vh.x;  SAh[so + 1] = vh.y;
        SAl[so] = vl.x;  SAl[so + 1] = vl.y;
    }
    // B copy (8192 words each buffer, uint4; conflict-free stores within rows)
    const uint4* W4h = (const uint4*)Whi;
    const uint4* W4l = (const uint4*)Wlo;
    #pragma unroll
    for (int p = 0; p < 8; p++) {
        int i4 = t + p * 256;
        int w = i4 * 4;
        int kp = w >> 7, nn = w & 127;
        uint4 vh = W4h[i4];
        uint4 vl = W4l[i4];
        int so = kp * PADB + nn;
        *(uint4*)(SBh + so) = vh;
        *(uint4*)(SBl + so) = vl;
    }
    __syncthreads();

    // warp wid: rows [rowg*16, +16), cols [colg*64, +64)
    int grp = lane >> 2, tig = lane & 3;
    int rowg = wid & 3, colg = wid >> 2;
    int abase = (rowg * 16 + grp) * PADA;
    float acc[8][4];
    #pragma unroll
    for (int i = 0; i < 8; i++)
        #pragma unroll
        for (int j = 0; j < 4; j++) acc[i][j] = 0.f;

    #pragma unroll
    for (int ks = 0; ks < 8; ks++) {
        int ak = ks * 8 + tig;
        unsigned ah[4], al[4];
        ah[0] = SAh[abase + ak];
        ah[1] = SAh[abase + 8 * PADA + ak];
        ah[2] = SAh[abase + ak + 4];
        ah[3] = SAh[abase + 8 * PADA + ak + 4];
        al[0] = SAl[abase + ak];
        al[1] = SAl[abase + 8 * PADA + ak];
        al[2] = SAl[abase + ak + 4];
        al[3] = SAl[abase + 8 * PADA + ak + 4];
        int bk0 = (ks * 8 + tig) * PADB + colg * 64 + grp;
        #pragma unroll
        for (int nt = 0; nt < 8; nt++) {
            int bi = bk0 + nt * 8;
            unsigned bh0 = SBh[bi], bh1 = SBh[bi + 4 * PADB];
            unsigned bl0 = SBl[bi], bl1 = SBl[bi + 4 * PADB];
            mma_bf16(acc[nt], ah, bh0, bh1);
            mma_bf16(acc[nt], ah, bl0, bl1);
            mma_bf16(acc[nt], al, bh0, bh1);
        }
    }

    int gr0 = row0 + rowg * 16 + grp;
    int gr1 = gr0 + 8;
    #pragma unroll
    for (int nt = 0; nt < 8; nt++) {
        int cc = colg * 64 + nt * 8 + 2 * tig;
        if (gr0 < n) *(float2*)(g_h1 + (size_t)gr0 * 128 + cc) = make_float2(acc[nt][0], acc[nt][1]);
        if (gr1 < n) *(float2*)(g_h1 + (size_t)gr1 * 128 + cc) = make_float2(acc[nt][2], acc[nt][3]);
    }
}

// ---------------- CSR aggregation: warp-per-node gather, fused bias+relu ----------------
// reads g_h1; mode 0 -> write split bf16 (g_hhi/g_hlo), mode 1 -> write fp32 g_h2
__global__ void __launch_bounds__(256) k_agg(const float* __restrict__ bias, int mode) {
    int gw = (blockIdx.x * blockDim.x + threadIdx.x) >> 5;
    if (gw >= NN) return;
    int lane = threadIdx.x & 31;
    const float4* h4 = (const float4*)g_h1;
    float di = g_dinv[gw];
    float4 own = h4[gw * 32 + lane];
    float ax = di * own.x, ay = di * own.y, az = di * own.z, aw = di * own.w;
    int e = g_rowptr[gw], end = g_rowptr[gw + 1];
    for (; e + 1 < end; e += 2) {
        int s0 = g_srcs[e];
        int s1 = g_srcs[e + 1];
        float c0 = g_dinv[s0];
        float c1 = g_dinv[s1];
        float4 v0 = h4[s0 * 32 + lane];
        float4 v1 = h4[s1 * 32 + lane];
        ax = fmaf(c0, v0.x, ax);  ay = fmaf(c0, v0.y, ay);
        az = fmaf(c0, v0.z, az);  aw = fmaf(c0, v0.w, aw);
        ax = fmaf(c1, v1.x, ax);  ay = fmaf(c1, v1.y, ay);
        az = fmaf(c1, v1.z, az);  aw = fmaf(c1, v1.w, aw);
    }
    if (e < end) {
        int s = g_srcs[e];
        float c = g_dinv[s];
        float4 v = h4[s * 32 + lane];
        ax = fmaf(c, v.x, ax);  ay = fmaf(c, v.y, ay);
        az = fmaf(c, v.z, az);  aw = fmaf(c, v.w, aw);
    }
    float4 b = ((const float4*)bias)[lane];
    float4 o;
    o.x = fmaxf(fmaf(di, ax, b.x), 0.f);
    o.y = fmaxf(fmaf(di, ay, b.y), 0.f);
    o.z = fmaxf(fmaf(di, az, b.z), 0.f);
    o.w = fmaxf(fmaf(di, aw, b.w), 0.f);
    if (mode == 0) {
        unsigned h0 = 0, l0 = 0, h1 = 0, l1 = 0;
        split2(o.x, h0, l0, 0);  split2(o.y, h0, l0, 16);
        split2(o.z, h1, l1, 0);  split2(o.w, h1, l1, 16);
        ((uint2*)g_hhi)[(size_t)gw * 32 + lane] = make_uint2(h0, h1);
        ((uint2*)g_hlo)[(size_t)gw * 32 + lane] = make_uint2(l0, l1);
    } else {
        ((float4*)g_h2)[gw * 32 + lane] = o;
    }
}

// ---------------- final: logits + log_softmax, warp-per-node (reads g_h2) ----------------
__global__ void __launch_bounds__(256) k_final(const float* __restrict__ Wf,
                                               const float* __restrict__ bf,
                                               float* __restrict__ out) {
    __shared__ float WfT[128 * 40];
    __shared__ float bfs[40];
    __shared__ __align__(16) float hs[8][128];
    int t = threadIdx.x;
    for (int e = t; e < NCLS * 128; e += 256) {
        int c = e >> 7, k = e & 127;
        WfT[k * 40 + c] = Wf[e];
    }
    if (t < NCLS) bfs[t] = bf[t];
    __syncthreads();

    int w = t >> 5, lane = t & 31;
    for (int node = blockIdx.x * 8 + w; node < NN; node += gridDim.x * 8) {
        ((float4*)hs[w])[lane] = ((const float4*)(g_h2 + (size_t)node * 128))[lane];
        __syncwarp();
        float acc0 = bfs[lane];
        float acc1 = (lane < 8) ? bfs[32 + lane] : 0.f;
        #pragma unroll 4
        for (int k = 0; k < 128; k++) {
            float hk = hs[w][k];
            acc0 = fmaf(hk, WfT[k * 40 + lane], acc0);
            if (lane < 8) acc1 = fmaf(hk, WfT[k * 40 + 32 + lane], acc1);
        }
        float m = acc0;
        if (lane < 8) m = fmaxf(m, acc1);
        #pragma unroll
        for (int off = 16; off; off >>= 1)
            m = fmaxf(m, __shfl_xor_sync(0xffffffffu, m, off));
        float s = __expf(acc0 - m) + ((lane < 8) ? __expf(acc1 - m) : 0.f);
        #pragma unroll
        for (int off = 16; off; off >>= 1)
            s += __shfl_xor_sync(0xffffffffu, s, off);
        float lse = m + __logf(s);
        out[(size_t)node * 40 + lane] = acc0 - lse;
        if (lane < 8) out[(size_t)node * 40 + 32 + lane] = acc1 - lse;
        __syncwarp();
    }
}

// ---------------- launch ----------------
extern "C" void kernel_launch(void* const* d_in, const int* in_sizes, int n_in,
                              void* d_out, int out_size) {
    const float* x  = (const float*)d_in[0];
    const int*   ei = (const int*)d_in[1];
    const float* W1 = (const float*)d_in[2];
    const float* b1 = (const float*)d_in[3];
    const float* W2 = (const float*)d_in[4];
    const float* b2 = (const float*)d_in[5];
    const float* Wf = (const float*)d_in[6];
    const float* bf = (const float*)d_in[7];
    float* out = (float*)d_out;

    const int* row = ei;        // sources
    const int* col = ei + EE;   // targets

    cudaFuncSetAttribute(k_mmagemm, cudaFuncAttributeMaxDynamicSharedMemorySize, SM_BYTES);
    int gblocks = (NN + 63) / 64;     // 782
    int ablocks = (NN * 32 + 255) / 256;

    // ncu captures launch #4 -> GEMM1 there
    k_splitW<<<64, 256>>>(W1, W2);                               // 1
    k_zero<<<(NN + 255) / 256, 256>>>();                         // 2
    k_splitx<<<(NN * 64 + 255) / 256, 256>>>(x);                 // 3
    k_mmagemm<<<gblocks, 256, SM_BYTES>>>(0, NN);                // 4 <- profiled
    k_hist<<<(EE + 255) / 256, 256>>>(col);                      // 5
    k_scan1<<<SCAN_NB, SCAN_BLK>>>();                            // 6
    k_scan2<<<1, SCAN_BLK>>>();                                  // 7
    k_scan3<<<SCAN_NB, SCAN_BLK>>>();                            // 8
    k_scatter<<<(EE + 255) / 256, 256>>>(row, col);              // 9
    k_agg<<<ablocks, 256>>>(b1, 0);                              // 10  -> g_hhi/g_hlo
    k_mmagemm<<<gblocks, 256, SM_BYTES>>>(1, NN);                // 11
    k_agg<<<ablocks, 256>>>(b2, 1);                              // 12  -> g_h2 fp32
    k_final<<<1184, 256>>>(Wf, bf, out);                         // 13
}

// round 13
// speedup vs baseline: 1.0534x; 1.0534x over previous
#include <cuda_runtime.h>
#include <cuda_bf16.h>
#include <cstdint>

#define NN 50000
#define EE 600000
#define DIM 128
#define NCLS 40
#define SCAN_BLK 256
#define SCAN_NB ((NN + SCAN_BLK - 1) / SCAN_BLK)   // 196

// ---------------- scratch (static __device__, no allocation) ----------------
__device__ int   g_cnt[NN];
__device__ int   g_rowptr[NN + 1];
__device__ int   g_fill[NN];
__device__ int   g_srcs[EE];
__device__ int   g_bsum[SCAN_NB];
__device__ int   g_boff[SCAN_NB];
__device__ float g_dinv[NN];
__device__ __align__(16) float g_h1[(size_t)NN * DIM];     // GEMM out (fp32)
__device__ __align__(16) float g_h2[(size_t)NN * DIM];     // layer2 agg out (fp32)
__device__ __align__(16) uint32_t g_hhi[(size_t)NN * 64];  // split agg1 out (bf16 pairs)
__device__ __align__(16) uint32_t g_hlo[(size_t)NN * 64];
__device__ __align__(16) uint32_t g_whi[2 * 8192];         // split W: [layer][n*64 + kpair]
__device__ __align__(16) uint32_t g_wlo[2 * 8192];

__device__ __forceinline__ void split2(float a, unsigned& hi, unsigned& lo, int sh) {
    __nv_bfloat16 hb = __float2bfloat16(a);
    float hf = __bfloat162float(hb);
    __nv_bfloat16 lb = __float2bfloat16(a - hf);
    hi |= (unsigned)__bfloat16_as_ushort(hb) << sh;
    lo |= (unsigned)__bfloat16_as_ushort(lb) << sh;
}

// ---------------- preprocessing ----------------
__global__ void k_zero() {
    int i = blockIdx.x * blockDim.x + threadIdx.x;
    if (i < NN) g_cnt[i] = 0;
}

__global__ void k_hist(const int* __restrict__ col) {
    int i = blockIdx.x * blockDim.x + threadIdx.x;
    if (i < EE) {
        unsigned c = (unsigned)col[i];
        if (c < NN) atomicAdd(&g_cnt[c], 1);
    }
}

__global__ void __launch_bounds__(SCAN_BLK) k_scan1() {
    __shared__ int ws[8];
    int t = threadIdx.x, lane = t & 31, w = t >> 5;
    int i = blockIdx.x * SCAN_BLK + t;
    int v = (i < NN) ? g_cnt[i] : 0;
    if (i < NN) g_dinv[i] = rsqrtf((float)v + 1.0f);
    int incl = v;
    #pragma unroll
    for (int off = 1; off < 32; off <<= 1) {
        int u = __shfl_up_sync(0xffffffffu, incl, off);
        if (lane >= off) incl += u;
    }
    if (lane == 31) ws[w] = incl;
    __syncthreads();
    if (w == 0 && lane < 8) {
        int s = ws[lane];
        #pragma unroll
        for (int off = 1; off < 8; off <<= 1) {
            int u = __shfl_up_sync(0xffu, s, off);
            if (lane >= off) s += u;
        }
        ws[lane] = s;
    }
    __syncthreads();
    int excl = incl - v + (w ? ws[w - 1] : 0);
    if (i < NN) g_rowptr[i] = excl;
    if (t == 0) g_bsum[blockIdx.x] = ws[7];
}

__global__ void __launch_bounds__(SCAN_BLK) k_scan2() {
    __shared__ int ws[8];
    int t = threadIdx.x, lane = t & 31, w = t >> 5;
    int v = (t < SCAN_NB) ? g_bsum[t] : 0;
    int incl = v;
    #pragma unroll
    for (int off = 1; off < 32; off <<= 1) {
        int u = __shfl_up_sync(0xffffffffu, incl, off);
        if (lane >= off) incl += u;
    }
    if (lane == 31) ws[w] = incl;
    __syncthreads();
    if (w == 0 && lane < 8) {
        int s = ws[lane];
        #pragma unroll
        for (int off = 1; off < 8; off <<= 1) {
            int u = __shfl_up_sync(0xffu, s, off);
            if (lane >= off) s += u;
        }
        ws[lane] = s;
    }
    __syncthreads();
    int excl = incl - v + (w ? ws[w - 1] : 0);
    if (t < SCAN_NB) g_boff[t] = excl;
    if (t == SCAN_NB - 1) g_rowptr[NN] = excl + v;
}

__global__ void __launch_bounds__(SCAN_BLK) k_scan3() {
    int i = blockIdx.x * SCAN_BLK + threadIdx.x;
    if (i < NN) {
        int e = g_rowptr[i] + g_boff[blockIdx.x];
        g_rowptr[i] = e;
        g_fill[i] = e;
    }
}

__global__ void k_scatter(const int* __restrict__ row,
                          const int* __restrict__ col) {
    int i = blockIdx.x * blockDim.x + threadIdx.x;
    if (i < EE) {
        unsigned c = (unsigned)col[i];
        unsigned r = (unsigned)row[i];
        if (c < NN && r < NN) {
            int p = atomicAdd(&g_fill[c], 1);
            g_srcs[p] = (int)r;
        }
    }
}

// ---------------- weight splitting ----------------
// g_whi layout: [layer][n*64 + kpair], word = bf16(k=2kp) | bf16(k=2kp+1)<<16
__global__ void k_splitW(const float* __restrict__ W1, const float* __restrict__ W2) {
    int i = blockIdx.x * blockDim.x + threadIdx.x;
    if (i >= 2 * 8192) return;
    const float* W = (i < 8192) ? W1 : W2;
    int j = i & 8191;                       // n*64 + kp
    int nn = j >> 6, kp = j & 63;
    float w0 = W[nn * 128 + 2 * kp];
    float w1 = W[nn * 128 + 2 * kp + 1];
    unsigned hi = 0, lo = 0;
    split2(w0, hi, lo, 0);
    split2(w1, hi, lo, 16);
    g_whi[i] = hi;
    g_wlo[i] = lo;
}

// ---------------- mma.sync GEMM via ldmatrix ----------------
// g_h1[n,128] = A[n,128] @ W[128,128]^T ; split-bf16 3-term, fp32 accumulate.
// smem (words, row stride 68 = 136 halves = 272B, 16B-aligned rows):
//   SAh[64][68] | SAl[64][68] | SBh[128][68] | SBl[128][68]
#define PADW 68
#define SA_LO_W (64 * PADW)                // 4352
#define SB_HI_W (2 * 64 * PADW)            // 8704
#define SB_LO_W (SB_HI_W + 128 * PADW)     // 17408
#define SMW_TOT (SB_LO_W + 128 * PADW)     // 26112 words
#define SM_BYTES (SMW_TOT * 4)             // 104448

__device__ __forceinline__ void mma_bf16(float* d, const unsigned* a, unsigned b0, unsigned b1) {
    asm volatile(
        "mma.sync.aligned.m16n8k16.row.col.f32.bf16.bf16.f32 "
        "{%0,%1,%2,%3}, {%4,%5,%6,%7}, {%8,%9}, {%0,%1,%2,%3};"
        : "+f"(d[0]), "+f"(d[1]), "+f"(d[2]), "+f"(d[3])
        : "r"(a[0]), "r"(a[1]), "r"(a[2]), "r"(a[3]), "r"(b0), "r"(b1));
}

#define LDSM_X4(r0, r1, r2, r3, addr) \
    asm volatile("ldmatrix.sync.aligned.m8n8.x4.shared.b16 {%0,%1,%2,%3}, [%4];" \
        : "=r"(r0), "=r"(r1), "=r"(r2), "=r"(r3) : "r"(addr))

__device__ __forceinline__ uint32_t smem_u32(const void* p) {
    uint32_t a;
    asm("{ .reg .u64 t; cvta.to.shared.u64 t, %1; cvt.u32.u64 %0, t; }" : "=r"(a) : "l"(p));
    return a;
}

__global__ void __launch_bounds__(256, 2)
k_mmagemm(const float* __restrict__ x, int layer, int n) {
    extern __shared__ __align__(16) uint32_t smw[];
    uint32_t* SAh = smw;
    uint32_t* SAl = smw + SA_LO_W;
    uint32_t* SBh = smw + SB_HI_W;
    uint32_t* SBl = smw + SB_LO_W;
    int t = threadIdx.x, wid = t >> 5, lane = t & 31;
    int row0 = blockIdx.x * 64;

    // ---- A tile fill (64 rows x 64 words per buffer) ----
    if (layer == 0) {
        const float4* X4 = (const float4*)x;
        #pragma unroll
        for (int p = 0; p < 8; p++) {
            int i2 = t + p * 256;            // 0..2047 (row, float4-index)
            int r = i2 >> 5, c2 = i2 & 31;
            int gr = row0 + r;
            if (gr >= n) gr = n - 1;
            float4 a = X4[(size_t)gr * 32 + c2];
            unsigned h0 = 0, l0 = 0, h1 = 0, l1 = 0;
            split2(a.x, h0, l0, 0);  split2(a.y, h0, l0, 16);
            split2(a.z, h1, l1, 0);  split2(a.w, h1, l1, 16);
            int so = r * PADW + c2 * 2;
            SAh[so] = h0;  SAh[so + 1] = h1;
            SAl[so] = l0;  SAl[so + 1] = l1;
        }
    } else {
        const uint2* A2h = (const uint2*)g_hhi;
        const uint2* A2l = (const uint2*)g_hlo;
        #pragma unroll
        for (int p = 0; p < 8; p++) {
            int i2 = t + p * 256;
            int r = i2 >> 5, c2 = i2 & 31;
            int gr = row0 + r;
            if (gr >= n) gr = n - 1;
            uint2 vh = A2h[(size_t)gr * 32 + c2];
            uint2 vl = A2l[(size_t)gr * 32 + c2];
            int so = r * PADW + c2 * 2;
            SAh[so] = vh.x;  SAh[so + 1] = vh.y;
            SAl[so] = vl.x;  SAl[so + 1] = vl.y;
        }
    }
    // ---- B fill: [n][kpair] natural layout, 8192 words per buffer ----
    {
        const uint4* W4h = (const uint4*)(g_whi + layer * 8192);
        const uint4* W4l = (const uint4*)(g_wlo + layer * 8192);
        #pragma unroll
        for (int p = 0; p < 8; p++) {
            int i4 = t + p * 256;            // 0..2047
            int w = i4 * 4;                  // word index 0..8191
            int nr = w >> 6, wc = w & 63;    // n row (0..127), word-in-row (0..63)
            uint4 vh = W4h[i4];
            uint4 vl = W4l[i4];
            int so = nr * PADW + wc;
            *(uint4*)(SBh + so) = vh;
            *(uint4*)(SBl + so) = vl;
        }
    }
    __syncthreads();

    // ---- compute: warp wid -> rows [rowg*16,+16), cols [colg*64,+64) ----
    int grp = lane >> 2, tig = lane & 3;
    int rowg = wid & 3, colg = wid >> 2;
    int lr = lane & 7, lg = lane >> 3;
    int rsel = (lg & 1) << 3;                // +8 rows for matrices 1,3
    int csel = (lg >> 1) << 2;               // +4 words (8 halves) for matrices 2,3
    uint32_t smb = smem_u32(smw);
    uint32_t aH = smb + (uint32_t)(((rowg * 16 + lr + rsel) * PADW + csel) * 4);
    uint32_t aL = aH + SA_LO_W * 4;
    uint32_t bH = smb + (uint32_t)((SB_HI_W + (colg * 64 + lr + rsel) * PADW + csel) * 4);
    const uint32_t bLd = (SB_LO_W - SB_HI_W) * 4;
    const uint32_t pstep = 16 * PADW * 4;    // 16 B-rows

    float acc[8][4];
    #pragma unroll
    for (int i = 0; i < 8; i++)
        #pragma unroll
        for (int j = 0; j < 4; j++) acc[i][j] = 0.f;

    #pragma unroll
    for (int ks = 0; ks < 8; ks++) {
        uint32_t kadd = ks * 32;             // 8 words = 16 halves
        unsigned ah[4], al[4];
        LDSM_X4(ah[0], ah[1], ah[2], ah[3], aH + kadd);
        LDSM_X4(al[0], al[1], al[2], al[3], aL + kadd);
        #pragma unroll
        for (int p = 0; p < 4; p++) {
            unsigned bh[4], bl[4];
            uint32_t ba = bH + p * pstep + kadd;
            LDSM_X4(bh[0], bh[1], bh[2], bh[3], ba);
            LDSM_X4(bl[0], bl[1], bl[2], bl[3], ba + bLd);
            // B pair = {(n,k), (n,k+8)} -> (m0,m2) for n-tile lo, (m1,m3) for n-tile hi
            mma_bf16(acc[2 * p],     ah, bh[0], bh[2]);
            mma_bf16(acc[2 * p],     ah, bl[0], bl[2]);
            mma_bf16(acc[2 * p],     al, bh[0], bh[2]);
            mma_bf16(acc[2 * p + 1], ah, bh[1], bh[3]);
            mma_bf16(acc[2 * p + 1], ah, bl[1], bl[3]);
            mma_bf16(acc[2 * p + 1], al, bh[1], bh[3]);
        }
    }

    // ---- epilogue ----
    int gr0 = row0 + rowg * 16 + grp;
    int gr1 = gr0 + 8;
    #pragma unroll
    for (int j = 0; j < 8; j++) {
        int cc = colg * 64 + (j >> 1) * 16 + (j & 1) * 8 + 2 * tig;
        if (gr0 < n) *(float2*)(g_h1 + (size_t)gr0 * 128 + cc) = make_float2(acc[j][0], acc[j][1]);
        if (gr1 < n) *(float2*)(g_h1 + (size_t)gr1 * 128 + cc) = make_float2(acc[j][2], acc[j][3]);
    }
}

// ---------------- CSR aggregation: warp-per-node gather, fused bias+relu ----------------
// reads g_h1; mode 0 -> write split bf16 (g_hhi/g_hlo), mode 1 -> write fp32 g_h2
__global__ void __launch_bounds__(256) k_agg(const float* __restrict__ bias, int mode) {
    int gw = (blockIdx.x * blockDim.x + threadIdx.x) >> 5;
    if (gw >= NN) return;
    int lane = threadIdx.x & 31;
    const float4* h4 = (const float4*)g_h1;
    float di = g_dinv[gw];
    float4 own = h4[gw * 32 + lane];
    float ax = di * own.x, ay = di * own.y, az = di * own.z, aw = di * own.w;
    int e = g_rowptr[gw], end = g_rowptr[gw + 1];
    for (; e + 1 < end; e += 2) {
        int s0 = g_srcs[e];
        int s1 = g_srcs[e + 1];
        float c0 = g_dinv[s0];
        float c1 = g_dinv[s1];
        float4 v0 = h4[s0 * 32 + lane];
        float4 v1 = h4[s1 * 32 + lane];
        ax = fmaf(c0, v0.x, ax);  ay = fmaf(c0, v0.y, ay);
        az = fmaf(c0, v0.z, az);  aw = fmaf(c0, v0.w, aw);
        ax = fmaf(c1, v1.x, ax);  ay = fmaf(c1, v1.y, ay);
        az = fmaf(c1, v1.z, az);  aw = fmaf(c1, v1.w, aw);
    }
    if (e < end) {
        int s = g_srcs[e];
        float c = g_dinv[s];
        float4 v = h4[s * 32 + lane];
        ax = fmaf(c, v.x, ax);  ay = fmaf(c, v.y, ay);
        az = fmaf(c, v.z, az);  aw = fmaf(c, v.w, aw);
    }
    float4 b = ((const float4*)bias)[lane];
    float4 o;
    o.x = fmaxf(fmaf(di, ax, b.x), 0.f);
    o.y = fmaxf(fmaf(di, ay, b.y), 0.f);
    o.z = fmaxf(fmaf(di, az, b.z), 0.f);
    o.w = fmaxf(fmaf(di, aw, b.w), 0.f);
    if (mode == 0) {
        unsigned h0 = 0, l0 = 0, h1 = 0, l1 = 0;
        split2(o.x, h0, l0, 0);  split2(o.y, h0, l0, 16);
        split2(o.z, h1, l1, 0);  split2(o.w, h1, l1, 16);
        ((uint2*)g_hhi)[(size_t)gw * 32 + lane] = make_uint2(h0, h1);
        ((uint2*)g_hlo)[(size_t)gw * 32 + lane] = make_uint2(l0, l1);
    } else {
        ((float4*)g_h2)[gw * 32 + lane] = o;
    }
}

// ---------------- final: logits + log_softmax, warp-per-node (reads g_h2) ----------------
__global__ void __launch_bounds__(256) k_final(const float* __restrict__ Wf,
                                               const float* __restrict__ bf,
                                               float* __restrict__ out) {
    __shared__ float WfT[128 * 40];
    __shared__ float bfs[40];
    __shared__ __align__(16) float hs[8][128];
    int t = threadIdx.x;
    for (int e = t; e < NCLS * 128; e += 256) {
        int c = e >> 7, k = e & 127;
        WfT[k * 40 + c] = Wf[e];
    }
    if (t < NCLS) bfs[t] = bf[t];
    __syncthreads();

    int w = t >> 5, lane = t & 31;
    for (int node = blockIdx.x * 8 + w; node < NN; node += gridDim.x * 8) {
        ((float4*)hs[w])[lane] = ((const float4*)(g_h2 + (size_t)node * 128))[lane];
        __syncwarp();
        float acc0 = bfs[lane];
        float acc1 = (lane < 8) ? bfs[32 + lane] : 0.f;
        #pragma unroll 4
        for (int k = 0; k < 128; k++) {
            float hk = hs[w][k];
            acc0 = fmaf(hk, WfT[k * 40 + lane], acc0);
            if (lane < 8) acc1 = fmaf(hk, WfT[k * 40 + 32 + lane], acc1);
        }
        float m = acc0;
        if (lane < 8) m = fmaxf(m, acc1);
        #pragma unroll
        for (int off = 16; off; off >>= 1)
            m = fmaxf(m, __shfl_xor_sync(0xffffffffu, m, off));
        float s = __expf(acc0 - m) + ((lane < 8) ? __expf(acc1 - m) : 0.f);
        #pragma unroll
        for (int off = 16; off; off >>= 1)
            s += __shfl_xor_sync(0xffffffffu, s, off);
        float lse = m + __logf(s);
        out[(size_t)node * 40 + lane] = acc0 - lse;
        if (lane < 8) out[(size_t)node * 40 + 32 + lane] = acc1 - lse;
        __syncwarp();
    }
}

// ---------------- launch ----------------
extern "C" void kernel_launch(void* const* d_in, const int* in_sizes, int n_in,
                              void* d_out, int out_size) {
    const float* x  = (const float*)d_in[0];
    const int*   ei = (const int*)d_in[1];
    const float* W1 = (const float*)d_in[2];
    const float* b1 = (const float*)d_in[3];
    const float* W2 = (const float*)d_in[4];
    const float* b2 = (const float*)d_in[5];
    const float* Wf = (const float*)d_in[6];
    const float* bf = (const float*)d_in[7];
    float* out = (float*)d_out;

    const int* row = ei;        // sources
    const int* col = ei + EE;   // targets

    cudaFuncSetAttribute(k_mmagemm, cudaFuncAttributeMaxDynamicSharedMemorySize, SM_BYTES);
    int gblocks = (NN + 63) / 64;     // 782
    int ablocks = (NN * 32 + 255) / 256;

    // ncu captures launch #4 -> GEMM1 there
    k_splitW<<<64, 256>>>(W1, W2);                               // 1
    k_zero<<<(NN + 255) / 256, 256>>>();                         // 2
    k_hist<<<(EE + 255) / 256, 256>>>(col);                      // 3
    k_mmagemm<<<gblocks, 256, SM_BYTES>>>(x, 0, NN);             // 4 <- profiled
    k_scan1<<<SCAN_NB, SCAN_BLK>>>();                            // 5
    k_scan2<<<1, SCAN_BLK>>>();                                  // 6
    k_scan3<<<SCAN_NB, SCAN_BLK>>>();                            // 7
    k_scatter<<<(EE + 255) / 256, 256>>>(row, col);              // 8
    k_agg<<<ablocks, 256>>>(b1, 0);                              // 9   -> g_hhi/g_hlo
    k_mmagemm<<<gblocks, 256, SM_BYTES>>>(x, 1, NN);             // 10
    k_agg<<<ablocks, 256>>>(b2, 1);                              // 11  -> g_h2 fp32
    k_final<<<1184, 256>>>(Wf, bf, out);                         // 12
}

// round 14
// speedup vs baseline: 1.0973x; 1.0417x over previous
#include <cuda_runtime.h>
#include <cuda_bf16.h>
#include <cstdint>

#define NN 50000
#define EE 600000
#define DIM 128
#define NCLS 40
#define SCAN_BLK 256
#define SCAN_NB ((NN + SCAN_BLK - 1) / SCAN_BLK)   // 196
#define NTILES ((NN + 63) / 64)                    // 782
#define GEMM_GRID 296

// ---------------- scratch (static __device__, no allocation) ----------------
__device__ int   g_cnt[NN];
__device__ int   g_rowptr[NN + 1];
__device__ int   g_fill[NN];
__device__ int   g_srcs[EE];
__device__ int   g_bsum[SCAN_NB];
__device__ int   g_boff[SCAN_NB];
__device__ float g_dinv[NN];
__device__ __align__(16) float g_h1[(size_t)NN * DIM];     // GEMM out (fp32)
__device__ __align__(16) uint32_t g_hhi[(size_t)NN * 64];  // split agg1 out (bf16 pairs)
__device__ __align__(16) uint32_t g_hlo[(size_t)NN * 64];
__device__ __align__(16) uint32_t g_whi[2 * 8192];         // split W: [layer][n*64 + kpair]
__device__ __align__(16) uint32_t g_wlo[2 * 8192];

__device__ __forceinline__ void split2(float a, unsigned& hi, unsigned& lo, int sh) {
    __nv_bfloat16 hb = __float2bfloat16(a);
    float hf = __bfloat162float(hb);
    __nv_bfloat16 lb = __float2bfloat16(a - hf);
    hi |= (unsigned)__bfloat16_as_ushort(hb) << sh;
    lo |= (unsigned)__bfloat16_as_ushort(lb) << sh;
}

// ---------------- preprocessing ----------------
__global__ void k_zero() {
    int i = blockIdx.x * blockDim.x + threadIdx.x;
    if (i < NN) g_cnt[i] = 0;
}

__global__ void k_hist(const int* __restrict__ col) {
    int i = blockIdx.x * blockDim.x + threadIdx.x;
    if (i < EE) {
        unsigned c = (unsigned)col[i];
        if (c < NN) atomicAdd(&g_cnt[c], 1);
    }
}

__global__ void __launch_bounds__(SCAN_BLK) k_scan1() {
    __shared__ int ws[8];
    int t = threadIdx.x, lane = t & 31, w = t >> 5;
    int i = blockIdx.x * SCAN_BLK + t;
    int v = (i < NN) ? g_cnt[i] : 0;
    if (i < NN) g_dinv[i] = rsqrtf((float)v + 1.0f);
    int incl = v;
    #pragma unroll
    for (int off = 1; off < 32; off <<= 1) {
        int u = __shfl_up_sync(0xffffffffu, incl, off);
        if (lane >= off) incl += u;
    }
    if (lane == 31) ws[w] = incl;
    __syncthreads();
    if (w == 0 && lane < 8) {
        int s = ws[lane];
        #pragma unroll
        for (int off = 1; off < 8; off <<= 1) {
            int u = __shfl_up_sync(0xffu, s, off);
            if (lane >= off) s += u;
        }
        ws[lane] = s;
    }
    __syncthreads();
    int excl = incl - v + (w ? ws[w - 1] : 0);
    if (i < NN) g_rowptr[i] = excl;
    if (t == 0) g_bsum[blockIdx.x] = ws[7];
}

__global__ void __launch_bounds__(SCAN_BLK) k_scan2() {
    __shared__ int ws[8];
    int t = threadIdx.x, lane = t & 31, w = t >> 5;
    int v = (t < SCAN_NB) ? g_bsum[t] : 0;
    int incl = v;
    #pragma unroll
    for (int off = 1; off < 32; off <<= 1) {
        int u = __shfl_up_sync(0xffffffffu, incl, off);
        if (lane >= off) incl += u;
    }
    if (lane == 31) ws[w] = incl;
    __syncthreads();
    if (w == 0 && lane < 8) {
        int s = ws[lane];
        #pragma unroll
        for (int off = 1; off < 8; off <<= 1) {
            int u = __shfl_up_sync(0xffu, s, off);
            if (lane >= off) s += u;
        }
        ws[lane] = s;
    }
    __syncthreads();
    int excl = incl - v + (w ? ws[w - 1] : 0);
    if (t < SCAN_NB) g_boff[t] = excl;
    if (t == SCAN_NB - 1) g_rowptr[NN] = excl + v;
}

__global__ void __launch_bounds__(SCAN_BLK) k_scan3() {
    int i = blockIdx.x * SCAN_BLK + threadIdx.x;
    if (i < NN) {
        int e = g_rowptr[i] + g_boff[blockIdx.x];
        g_rowptr[i] = e;
        g_fill[i] = e;
    }
}

__global__ void k_scatter(const int* __restrict__ row,
                          const int* __restrict__ col) {
    int i = blockIdx.x * blockDim.x + threadIdx.x;
    if (i < EE) {
        unsigned c = (unsigned)col[i];
        unsigned r = (unsigned)row[i];
        if (c < NN && r < NN) {
            int p = atomicAdd(&g_fill[c], 1);
            g_srcs[p] = (int)r;
        }
    }
}

// ---------------- weight splitting ----------------
// g_whi layout: [layer][n*64 + kpair], word = bf16(k=2kp) | bf16(k=2kp+1)<<16
__global__ void k_splitW(const float* __restrict__ W1, const float* __restrict__ W2) {
    int i = blockIdx.x * blockDim.x + threadIdx.x;
    if (i >= 2 * 8192) return;
    const float* W = (i < 8192) ? W1 : W2;
    int j = i & 8191;                       // n*64 + kp
    int nn = j >> 6, kp = j & 63;
    float w0 = W[nn * 128 + 2 * kp];
    float w1 = W[nn * 128 + 2 * kp + 1];
    unsigned hi = 0, lo = 0;
    split2(w0, hi, lo, 0);
    split2(w1, hi, lo, 16);
    g_whi[i] = hi;
    g_wlo[i] = lo;
}

// ---------------- persistent mma.sync GEMM via ldmatrix ----------------
// g_h1[n,128] = A[n,128] @ W[128,128]^T ; split-bf16 3-term, fp32 accumulate.
// B loaded ONCE per CTA; loop over M-tiles stride gridDim.
#define PADW 68
#define SA_LO_W (64 * PADW)                // 4352
#define SB_HI_W (2 * 64 * PADW)            // 8704
#define SB_LO_W (SB_HI_W + 128 * PADW)     // 17408
#define SMW_TOT (SB_LO_W + 128 * PADW)     // 26112 words
#define SM_BYTES (SMW_TOT * 4)             // 104448

__device__ __forceinline__ void mma_bf16(float* d, const unsigned* a, unsigned b0, unsigned b1) {
    asm volatile(
        "mma.sync.aligned.m16n8k16.row.col.f32.bf16.bf16.f32 "
        "{%0,%1,%2,%3}, {%4,%5,%6,%7}, {%8,%9}, {%0,%1,%2,%3};"
        : "+f"(d[0]), "+f"(d[1]), "+f"(d[2]), "+f"(d[3])
        : "r"(a[0]), "r"(a[1]), "r"(a[2]), "r"(a[3]), "r"(b0), "r"(b1));
}

#define LDSM_X4(r0, r1, r2, r3, addr) \
    asm volatile("ldmatrix.sync.aligned.m8n8.x4.shared.b16 {%0,%1,%2,%3}, [%4];" \
        : "=r"(r0), "=r"(r1), "=r"(r2), "=r"(r3) : "r"(addr))

__device__ __forceinline__ uint32_t smem_u32(const void* p) {
    uint32_t a;
    asm("{ .reg .u64 t; cvta.to.shared.u64 t, %1; cvt.u32.u64 %0, t; }" : "=r"(a) : "l"(p));
    return a;
}

__global__ void __launch_bounds__(256, 2)
k_mmagemm(const float* __restrict__ x, int layer, int n) {
    extern __shared__ __align__(16) uint32_t smw[];
    uint32_t* SAh = smw;
    uint32_t* SAl = smw + SA_LO_W;
    uint32_t* SBh = smw + SB_HI_W;
    uint32_t* SBl = smw + SB_LO_W;
    int t = threadIdx.x, wid = t >> 5, lane = t & 31;

    // ---- B fill ONCE: [n][kpair] natural layout, 8192 words per buffer ----
    {
        const uint4* W4h = (const uint4*)(g_whi + layer * 8192);
        const uint4* W4l = (const uint4*)(g_wlo + layer * 8192);
        #pragma unroll
        for (int p = 0; p < 8; p++) {
            int i4 = t + p * 256;            // 0..2047
            int w = i4 * 4;
            int nr = w >> 6, wc = w & 63;
            uint4 vh = W4h[i4];
            uint4 vl = W4l[i4];
            int so = nr * PADW + wc;
            *(uint4*)(SBh + so) = vh;
            *(uint4*)(SBl + so) = vl;
        }
    }

    // compute-lane constants
    int grp = lane >> 2, tig = lane & 3;
    int rowg = wid & 3, colg = wid >> 2;
    int lr = lane & 7, lg = lane >> 3;
    int rsel = (lg & 1) << 3;
    int csel = (lg >> 1) << 2;
    uint32_t smb = smem_u32(smw);
    uint32_t aHb = smb + (uint32_t)(((rowg * 16 + lr + rsel) * PADW + csel) * 4);
    uint32_t aLb = aHb + SA_LO_W * 4;
    uint32_t bH = smb + (uint32_t)((SB_HI_W + (colg * 64 + lr + rsel) * PADW + csel) * 4);
    const uint32_t bLd = (SB_LO_W - SB_HI_W) * 4;
    const uint32_t pstep = 16 * PADW * 4;

    for (int tile = blockIdx.x; tile < NTILES; tile += gridDim.x) {
        int row0 = tile * 64;
        __syncthreads();   // prior compute done reading SA (and first pass: nothing)

        // ---- A tile fill ----
        if (layer == 0) {
            const float4* X4 = (const float4*)x;
            #pragma unroll
            for (int p = 0; p < 8; p++) {
                int i2 = t + p * 256;
                int r = i2 >> 5, c2 = i2 & 31;
                int gr = row0 + r;
                if (gr >= n) gr = n - 1;
                float4 a = X4[(size_t)gr * 32 + c2];
                unsigned h0 = 0, l0 = 0, h1 = 0, l1 = 0;
                split2(a.x, h0, l0, 0);  split2(a.y, h0, l0, 16);
                split2(a.z, h1, l1, 0);  split2(a.w, h1, l1, 16);
                int so = r * PADW + c2 * 2;
                SAh[so] = h0;  SAh[so + 1] = h1;
                SAl[so] = l0;  SAl[so + 1] = l1;
            }
        } else {
            const uint2* A2h = (const uint2*)g_hhi;
            const uint2* A2l = (const uint2*)g_hlo;
            #pragma unroll
            for (int p = 0; p < 8; p++) {
                int i2 = t + p * 256;
                int r = i2 >> 5, c2 = i2 & 31;
                int gr = row0 + r;
                if (gr >= n) gr = n - 1;
                uint2 vh = A2h[(size_t)gr * 32 + c2];
                uint2 vl = A2l[(size_t)gr * 32 + c2];
                int so = r * PADW + c2 * 2;
                SAh[so] = vh.x;  SAh[so + 1] = vh.y;
                SAl[so] = vl.x;  SAl[so + 1] = vl.y;
            }
        }
        __syncthreads();   // A ready (first pass: also covers B)

        float acc[8][4];
        #pragma unroll
        for (int i = 0; i < 8; i++)
            #pragma unroll
            for (int j = 0; j < 4; j++) acc[i][j] = 0.f;

        #pragma unroll
        for (int ks = 0; ks < 8; ks++) {
            uint32_t kadd = ks * 32;
            unsigned ah[4], al[4];
            LDSM_X4(ah[0], ah[1], ah[2], ah[3], aHb + kadd);
            LDSM_X4(al[0], al[1], al[2], al[3], aLb + kadd);
            #pragma unroll
            for (int p = 0; p < 4; p++) {
                unsigned bh[4], bl[4];
                uint32_t ba = bH + p * pstep + kadd;
                LDSM_X4(bh[0], bh[1], bh[2], bh[3], ba);
                LDSM_X4(bl[0], bl[1], bl[2], bl[3], ba + bLd);
                mma_bf16(acc[2 * p],     ah, bh[0], bh[2]);
                mma_bf16(acc[2 * p],     ah, bl[0], bl[2]);
                mma_bf16(acc[2 * p],     al, bh[0], bh[2]);
                mma_bf16(acc[2 * p + 1], ah, bh[1], bh[3]);
                mma_bf16(acc[2 * p + 1], ah, bl[1], bl[3]);
                mma_bf16(acc[2 * p + 1], al, bh[1], bh[3]);
            }
        }

        int gr0 = row0 + rowg * 16 + grp;
        int gr1 = gr0 + 8;
        #pragma unroll
        for (int j = 0; j < 8; j++) {
            int cc = colg * 64 + (j >> 1) * 16 + (j & 1) * 8 + 2 * tig;
            if (gr0 < n) *(float2*)(g_h1 + (size_t)gr0 * 128 + cc) = make_float2(acc[j][0], acc[j][1]);
            if (gr1 < n) *(float2*)(g_h1 + (size_t)gr1 * 128 + cc) = make_float2(acc[j][2], acc[j][3]);
        }
    }
}

// ---------------- agg layer 1: gather + bias + relu -> split bf16 ----------------
__global__ void __launch_bounds__(256) k_agg1(const float* __restrict__ bias) {
    int gw = (blockIdx.x * blockDim.x + threadIdx.x) >> 5;
    if (gw >= NN) return;
    int lane = threadIdx.x & 31;
    const float4* h4 = (const float4*)g_h1;
    float di = g_dinv[gw];
    float4 own = h4[gw * 32 + lane];
    float ax = di * own.x, ay = di * own.y, az = di * own.z, aw = di * own.w;
    int e = g_rowptr[gw], end = g_rowptr[gw + 1];
    for (; e + 1 < end; e += 2) {
        int s0 = g_srcs[e];
        int s1 = g_srcs[e + 1];
        float c0 = g_dinv[s0];
        float c1 = g_dinv[s1];
        float4 v0 = h4[s0 * 32 + lane];
        float4 v1 = h4[s1 * 32 + lane];
        ax = fmaf(c0, v0.x, ax);  ay = fmaf(c0, v0.y, ay);
        az = fmaf(c0, v0.z, az);  aw = fmaf(c0, v0.w, aw);
        ax = fmaf(c1, v1.x, ax);  ay = fmaf(c1, v1.y, ay);
        az = fmaf(c1, v1.z, az);  aw = fmaf(c1, v1.w, aw);
    }
    if (e < end) {
        int s = g_srcs[e];
        float c = g_dinv[s];
        float4 v = h4[s * 32 + lane];
        ax = fmaf(c, v.x, ax);  ay = fmaf(c, v.y, ay);
        az = fmaf(c, v.z, az);  aw = fmaf(c, v.w, aw);
    }
    float4 b = ((const float4*)bias)[lane];
    float ox = fmaxf(fmaf(di, ax, b.x), 0.f);
    float oy = fmaxf(fmaf(di, ay, b.y), 0.f);
    float oz = fmaxf(fmaf(di, az, b.z), 0.f);
    float ow = fmaxf(fmaf(di, aw, b.w), 0.f);
    unsigned h0 = 0, l0 = 0, h1 = 0, l1 = 0;
    split2(ox, h0, l0, 0);  split2(oy, h0, l0, 16);
    split2(oz, h1, l1, 0);  split2(ow, h1, l1, 16);
    ((uint2*)g_hhi)[(size_t)gw * 32 + lane] = make_uint2(h0, h1);
    ((uint2*)g_hlo)[(size_t)gw * 32 + lane] = make_uint2(l0, l1);
}

// ---------------- fused agg layer 2 + final (logits + log_softmax) ----------------
__global__ void __launch_bounds__(256) k_aggfinal(const float* __restrict__ bias,
                                                 const float* __restrict__ Wf,
                                                 const float* __restrict__ bf,
                                                 float* __restrict__ out) {
    __shared__ float WfT[128 * 40];
    __shared__ float bfs[40];
    __shared__ __align__(16) float hs[8][128];
    int t = threadIdx.x;
    for (int e = t; e < NCLS * 128; e += 256) {
        int c = e >> 7, k = e & 127;
        WfT[k * 40 + c] = Wf[e];
    }
    if (t < NCLS) bfs[t] = bf[t];
    __syncthreads();

    int w = t >> 5, lane = t & 31;
    const float4* h4 = (const float4*)g_h1;
    float4 b = ((const float4*)bias)[lane];

    for (int node = blockIdx.x * 8 + w; node < NN; node += gridDim.x * 8) {
        // ---- aggregation for this node ----
        float di = g_dinv[node];
        float4 own = h4[node * 32 + lane];
        float ax = di * own.x, ay = di * own.y, az = di * own.z, aw = di * own.w;
        int e = g_rowptr[node], end = g_rowptr[node + 1];
        for (; e + 1 < end; e += 2) {
            int s0 = g_srcs[e];
            int s1 = g_srcs[e + 1];
            float c0 = g_dinv[s0];
            float c1 = g_dinv[s1];
            float4 v0 = h4[s0 * 32 + lane];
            float4 v1 = h4[s1 * 32 + lane];
            ax = fmaf(c0, v0.x, ax);  ay = fmaf(c0, v0.y, ay);
            az = fmaf(c0, v0.z, az);  aw = fmaf(c0, v0.w, aw);
            ax = fmaf(c1, v1.x, ax);  ay = fmaf(c1, v1.y, ay);
            az = fmaf(c1, v1.z, az);  aw = fmaf(c1, v1.w, aw);
        }
        if (e < end) {
            int s = g_srcs[e];
            float c = g_dinv[s];
            float4 v = h4[s * 32 + lane];
            ax = fmaf(c, v.x, ax);  ay = fmaf(c, v.y, ay);
            az = fmaf(c, v.z, az);  aw = fmaf(c, v.w, aw);
        }
        float4 o;
        o.x = fmaxf(fmaf(di, ax, b.x), 0.f);
        o.y = fmaxf(fmaf(di, ay, b.y), 0.f);
        o.z = fmaxf(fmaf(di, az, b.z), 0.f);
        o.w = fmaxf(fmaf(di, aw, b.w), 0.f);
        ((float4*)hs[w])[lane] = o;
        __syncwarp();

        // ---- logits + log_softmax ----
        float acc0 = bfs[lane];
        float acc1 = (lane < 8) ? bfs[32 + lane] : 0.f;
        #pragma unroll 4
        for (int k = 0; k < 128; k++) {
            float hk = hs[w][k];
            acc0 = fmaf(hk, WfT[k * 40 + lane], acc0);
            if (lane < 8) acc1 = fmaf(hk, WfT[k * 40 + 32 + lane], acc1);
        }
        float m = acc0;
        if (lane < 8) m = fmaxf(m, acc1);
        #pragma unroll
        for (int off = 16; off; off >>= 1)
            m = fmaxf(m, __shfl_xor_sync(0xffffffffu, m, off));
        float s = __expf(acc0 - m) + ((lane < 8) ? __expf(acc1 - m) : 0.f);
        #pragma unroll
        for (int off = 16; off; off >>= 1)
            s += __shfl_xor_sync(0xffffffffu, s, off);
        float lse = m + __logf(s);
        out[(size_t)node * 40 + lane] = acc0 - lse;
        if (lane < 8) out[(size_t)node * 40 + 32 + lane] = acc1 - lse;
        __syncwarp();
    }
}

// ---------------- launch ----------------
extern "C" void kernel_launch(void* const* d_in, const int* in_sizes, int n_in,
                              void* d_out, int out_size) {
    const float* x  = (const float*)d_in[0];
    const int*   ei = (const int*)d_in[1];
    const float* W1 = (const float*)d_in[2];
    const float* b1 = (const float*)d_in[3];
    const float* W2 = (const float*)d_in[4];
    const float* b2 = (const float*)d_in[5];
    const float* Wf = (const float*)d_in[6];
    const float* bf = (const float*)d_in[7];
    float* out = (float*)d_out;

    const int* row = ei;        // sources
    const int* col = ei + EE;   // targets

    cudaFuncSetAttribute(k_mmagemm, cudaFuncAttributeMaxDynamicSharedMemorySize, SM_BYTES);
    int ablocks = (NN * 32 + 255) / 256;

    // ncu captures launch #4 -> GEMM1 there
    k_splitW<<<64, 256>>>(W1, W2);                               // 1
    k_zero<<<(NN + 255) / 256, 256>>>();                         // 2
    k_hist<<<(EE + 255) / 256, 256>>>(col);                      // 3
    k_mmagemm<<<GEMM_GRID, 256, SM_BYTES>>>(x, 0, NN);           // 4 <- profiled
    k_scan1<<<SCAN_NB, SCAN_BLK>>>();                            // 5
    k_scan2<<<1, SCAN_BLK>>>();                                  // 6
    k_scan3<<<SCAN_NB, SCAN_BLK>>>();                            // 7
    k_scatter<<<(EE + 255) / 256, 256>>>(row, col);              // 8
    k_agg1<<<ablocks, 256>>>(b1);                                // 9   -> g_hhi/g_hlo
    k_mmagemm<<<GEMM_GRID, 256, SM_BYTES>>>(x, 1, NN);           // 10
    k_aggfinal<<<1184, 256>>>(b2, Wf, bf, out);                  // 11
}

// round 15
// speedup vs baseline: 1.1043x; 1.0064x over previous
#include <cuda_runtime.h>
#include <cuda_bf16.h>
#include <cstdint>

#define NN 50000
#define EE 600000
#define DIM 128
#define NCLS 40
#define SCAN_BLK 256
#define SCAN_NB ((NN + SCAN_BLK - 1) / SCAN_BLK)   // 196
#define NTILES ((NN + 63) / 64)                    // 782
#define GEMM_GRID 444                              // 222 CTAs per N-half

// ---------------- scratch (static __device__, no allocation) ----------------
__device__ int   g_cnt[NN];
__device__ int   g_rowptr[NN + 1];
__device__ int   g_fill[NN];
__device__ int   g_srcs[EE];
__device__ int   g_bsum[SCAN_NB];
__device__ int   g_boff[SCAN_NB];
__device__ float g_dinv[NN];
__device__ __align__(16) float g_h1[(size_t)NN * DIM];     // GEMM out (fp32)
__device__ __align__(16) uint32_t g_hhi[(size_t)NN * 64];  // split agg1 out (bf16 pairs)
__device__ __align__(16) uint32_t g_hlo[(size_t)NN * 64];
__device__ __align__(16) uint32_t g_whi[2 * 8192];         // split W: [layer][n*64 + kpair]
__device__ __align__(16) uint32_t g_wlo[2 * 8192];

__device__ __forceinline__ void split2(float a, unsigned& hi, unsigned& lo, int sh) {
    __nv_bfloat16 hb = __float2bfloat16(a);
    float hf = __bfloat162float(hb);
    __nv_bfloat16 lb = __float2bfloat16(a - hf);
    hi |= (unsigned)__bfloat16_as_ushort(hb) << sh;
    lo |= (unsigned)__bfloat16_as_ushort(lb) << sh;
}

// ---------------- preprocessing ----------------
__global__ void k_zero() {
    int i = blockIdx.x * blockDim.x + threadIdx.x;
    if (i < NN) g_cnt[i] = 0;
}

__global__ void k_hist(const int* __restrict__ col) {
    int i = blockIdx.x * blockDim.x + threadIdx.x;
    if (i < EE) {
        unsigned c = (unsigned)col[i];
        if (c < NN) atomicAdd(&g_cnt[c], 1);
    }
}

__global__ void __launch_bounds__(SCAN_BLK) k_scan1() {
    __shared__ int ws[8];
    int t = threadIdx.x, lane = t & 31, w = t >> 5;
    int i = blockIdx.x * SCAN_BLK + t;
    int v = (i < NN) ? g_cnt[i] : 0;
    if (i < NN) g_dinv[i] = rsqrtf((float)v + 1.0f);
    int incl = v;
    #pragma unroll
    for (int off = 1; off < 32; off <<= 1) {
        int u = __shfl_up_sync(0xffffffffu, incl, off);
        if (lane >= off) incl += u;
    }
    if (lane == 31) ws[w] = incl;
    __syncthreads();
    if (w == 0 && lane < 8) {
        int s = ws[lane];
        #pragma unroll
        for (int off = 1; off < 8; off <<= 1) {
            int u = __shfl_up_sync(0xffu, s, off);
            if (lane >= off) s += u;
        }
        ws[lane] = s;
    }
    __syncthreads();
    int excl = incl - v + (w ? ws[w - 1] : 0);
    if (i < NN) g_rowptr[i] = excl;
    if (t == 0) g_bsum[blockIdx.x] = ws[7];
}

__global__ void __launch_bounds__(SCAN_BLK) k_scan2() {
    __shared__ int ws[8];
    int t = threadIdx.x, lane = t & 31, w = t >> 5;
    int v = (t < SCAN_NB) ? g_bsum[t] : 0;
    int incl = v;
    #pragma unroll
    for (int off = 1; off < 32; off <<= 1) {
        int u = __shfl_up_sync(0xffffffffu, incl, off);
        if (lane >= off) incl += u;
    }
    if (lane == 31) ws[w] = incl;
    __syncthreads();
    if (w == 0 && lane < 8) {
        int s = ws[lane];
        #pragma unroll
        for (int off = 1; off < 8; off <<= 1) {
            int u = __shfl_up_sync(0xffu, s, off);
            if (lane >= off) s += u;
        }
        ws[lane] = s;
    }
    __syncthreads();
    int excl = incl - v + (w ? ws[w - 1] : 0);
    if (t < SCAN_NB) g_boff[t] = excl;
    if (t == SCAN_NB - 1) g_rowptr[NN] = excl + v;
}

__global__ void __launch_bounds__(SCAN_BLK) k_scan3() {
    int i = blockIdx.x * SCAN_BLK + threadIdx.x;
    if (i < NN) {
        int e = g_rowptr[i] + g_boff[blockIdx.x];
        g_rowptr[i] = e;
        g_fill[i] = e;
    }
}

__global__ void k_scatter(const int* __restrict__ row,
                          const int* __restrict__ col) {
    int i = blockIdx.x * blockDim.x + threadIdx.x;
    if (i < EE) {
        unsigned c = (unsigned)col[i];
        unsigned r = (unsigned)row[i];
        if (c < NN && r < NN) {
            int p = atomicAdd(&g_fill[c], 1);
            g_srcs[p] = (int)r;
        }
    }
}

// ---------------- weight splitting ----------------
// g_whi layout: [layer][n*64 + kpair], word = bf16(k=2kp) | bf16(k=2kp+1)<<16
__global__ void k_splitW(const float* __restrict__ W1, const float* __restrict__ W2) {
    int i = blockIdx.x * blockDim.x + threadIdx.x;
    if (i >= 2 * 8192) return;
    const float* W = (i < 8192) ? W1 : W2;
    int j = i & 8191;                       // n*64 + kp
    int nn = j >> 6, kp = j & 63;
    float w0 = W[nn * 128 + 2 * kp];
    float w1 = W[nn * 128 + 2 * kp + 1];
    unsigned hi = 0, lo = 0;
    split2(w0, hi, lo, 0);
    split2(w1, hi, lo, 16);
    g_whi[i] = hi;
    g_wlo[i] = lo;
}

// ---------------- persistent N-split mma.sync GEMM via ldmatrix ----------------
// g_h1[n,128] = A[n,128] @ W[128,128]^T ; split-bf16 3-term, fp32 accumulate.
// Each CTA owns one 64-col N-half of W (loaded once), loops over M-tiles.
// smem: SAh[64][68] | SAl[64][68] | SBh[64][68] | SBl[64][68]  = 69632 B -> 3 CTAs/SM
#define PADW 68
#define SA_LO_W (64 * PADW)                // 4352
#define SB_HI_W (2 * 64 * PADW)            // 8704
#define SB_LO_W (SB_HI_W + 64 * PADW)      // 13056
#define SMW_TOT (SB_LO_W + 64 * PADW)      // 17408 words
#define SM_BYTES (SMW_TOT * 4)             // 69632

__device__ __forceinline__ void mma_bf16(float* d, const unsigned* a, unsigned b0, unsigned b1) {
    asm volatile(
        "mma.sync.aligned.m16n8k16.row.col.f32.bf16.bf16.f32 "
        "{%0,%1,%2,%3}, {%4,%5,%6,%7}, {%8,%9}, {%0,%1,%2,%3};"
        : "+f"(d[0]), "+f"(d[1]), "+f"(d[2]), "+f"(d[3])
        : "r"(a[0]), "r"(a[1]), "r"(a[2]), "r"(a[3]), "r"(b0), "r"(b1));
}

#define LDSM_X4(r0, r1, r2, r3, addr) \
    asm volatile("ldmatrix.sync.aligned.m8n8.x4.shared.b16 {%0,%1,%2,%3}, [%4];" \
        : "=r"(r0), "=r"(r1), "=r"(r2), "=r"(r3) : "r"(addr))

__device__ __forceinline__ uint32_t smem_u32(const void* p) {
    uint32_t a;
    asm("{ .reg .u64 t; cvta.to.shared.u64 t, %1; cvt.u32.u64 %0, t; }" : "=r"(a) : "l"(p));
    return a;
}

__global__ void __launch_bounds__(256, 3)
k_mmagemm(const float* __restrict__ x, int layer, int n) {
    extern __shared__ __align__(16) uint32_t smw[];
    uint32_t* SAh = smw;
    uint32_t* SAl = smw + SA_LO_W;
    uint32_t* SBh = smw + SB_HI_W;
    uint32_t* SBl = smw + SB_LO_W;
    int t = threadIdx.x, wid = t >> 5, lane = t & 31;
    int halfN = blockIdx.x & 1;              // fixed per CTA
    int cta   = blockIdx.x >> 1;             // 0..221
    int ctas  = gridDim.x >> 1;              // 222

    // ---- B-half fill ONCE: rows [halfN*64, +64), 4096 words per buffer ----
    {
        const uint4* W4h = (const uint4*)(g_whi + layer * 8192 + halfN * 64 * 64);
        const uint4* W4l = (const uint4*)(g_wlo + layer * 8192 + halfN * 64 * 64);
        #pragma unroll
        for (int p = 0; p < 4; p++) {
            int i4 = t + p * 256;            // 0..1023
            int w = i4 * 4;                  // word 0..4095
            int nr = w >> 6, wc = w & 63;
            uint4 vh = W4h[i4];
            uint4 vl = W4l[i4];
            int so = nr * PADW + wc;
            *(uint4*)(SBh + so) = vh;
            *(uint4*)(SBl + so) = vl;
        }
    }

    // compute-lane constants
    int grp = lane >> 2, tig = lane & 3;
    int rowg = wid & 3, colg = wid >> 2;     // colg 0..1 (32 cols each)
    int lr = lane & 7, lg = lane >> 3;
    int rsel = (lg & 1) << 3;
    int csel = (lg >> 1) << 2;
    uint32_t smb = smem_u32(smw);
    uint32_t aHb = smb + (uint32_t)(((rowg * 16 + lr + rsel) * PADW + csel) * 4);
    uint32_t aLb = aHb + SA_LO_W * 4;
    uint32_t bH = smb + (uint32_t)((SB_HI_W + (colg * 32 + lr + rsel) * PADW + csel) * 4);
    const uint32_t bLd = (SB_LO_W - SB_HI_W) * 4;
    const uint32_t pstep = 16 * PADW * 4;

    for (int tile = cta; tile < NTILES; tile += ctas) {
        int row0 = tile * 64;
        __syncthreads();   // prior compute done reading SA (first pass: also orders B)

        // ---- A tile fill (full K, 64 rows) ----
        if (layer == 0) {
            const float4* X4 = (const float4*)x;
            #pragma unroll
            for (int p = 0; p < 8; p++) {
                int i2 = t + p * 256;
                int r = i2 >> 5, c2 = i2 & 31;
                int gr = row0 + r;
                if (gr >= n) gr = n - 1;
                float4 a = X4[(size_t)gr * 32 + c2];
                unsigned h0 = 0, l0 = 0, h1 = 0, l1 = 0;
                split2(a.x, h0, l0, 0);  split2(a.y, h0, l0, 16);
                split2(a.z, h1, l1, 0);  split2(a.w, h1, l1, 16);
                int so = r * PADW + c2 * 2;
                SAh[so] = h0;  SAh[so + 1] = h1;
                SAl[so] = l0;  SAl[so + 1] = l1;
            }
        } else {
            const uint2* A2h = (const uint2*)g_hhi;
            const uint2* A2l = (const uint2*)g_hlo;
            #pragma unroll
            for (int p = 0; p < 8; p++) {
                int i2 = t + p * 256;
                int r = i2 >> 5, c2 = i2 & 31;
                int gr = row0 + r;
                if (gr >= n) gr = n - 1;
                uint2 vh = A2h[(size_t)gr * 32 + c2];
                uint2 vl = A2l[(size_t)gr * 32 + c2];
                int so = r * PADW + c2 * 2;
                SAh[so] = vh.x;  SAh[so + 1] = vh.y;
                SAl[so] = vl.x;  SAl[so + 1] = vl.y;
            }
        }
        __syncthreads();   // A ready

        float acc[4][4];
        #pragma unroll
        for (int i = 0; i < 4; i++)
            #pragma unroll
            for (int j = 0; j < 4; j++) acc[i][j] = 0.f;

        #pragma unroll
        for (int ks = 0; ks < 8; ks++) {
            uint32_t kadd = ks * 32;
            unsigned ah[4], al[4];
            LDSM_X4(ah[0], ah[1], ah[2], ah[3], aHb + kadd);
            LDSM_X4(al[0], al[1], al[2], al[3], aLb + kadd);
            #pragma unroll
            for (int p = 0; p < 2; p++) {
                unsigned bh[4], bl[4];
                uint32_t ba = bH + p * pstep + kadd;
                LDSM_X4(bh[0], bh[1], bh[2], bh[3], ba);
                LDSM_X4(bl[0], bl[1], bl[2], bl[3], ba + bLd);
                // B pair = {(n,k), (n,k+8)} -> (m0,m2) n-tile lo, (m1,m3) n-tile hi
                mma_bf16(acc[2 * p],     ah, bh[0], bh[2]);
                mma_bf16(acc[2 * p],     ah, bl[0], bl[2]);
                mma_bf16(acc[2 * p],     al, bh[0], bh[2]);
                mma_bf16(acc[2 * p + 1], ah, bh[1], bh[3]);
                mma_bf16(acc[2 * p + 1], ah, bl[1], bl[3]);
                mma_bf16(acc[2 * p + 1], al, bh[1], bh[3]);
            }
        }

        int gr0 = row0 + rowg * 16 + grp;
        int gr1 = gr0 + 8;
        #pragma unroll
        for (int j = 0; j < 4; j++) {
            int cc = halfN * 64 + colg * 32 + (j >> 1) * 16 + (j & 1) * 8 + 2 * tig;
            if (gr0 < n) *(float2*)(g_h1 + (size_t)gr0 * 128 + cc) = make_float2(acc[j][0], acc[j][1]);
            if (gr1 < n) *(float2*)(g_h1 + (size_t)gr1 * 128 + cc) = make_float2(acc[j][2], acc[j][3]);
        }
    }
}

// ---------------- agg layer 1: gather + bias + relu -> split bf16 ----------------
__global__ void __launch_bounds__(256) k_agg1(const float* __restrict__ bias) {
    int gw = (blockIdx.x * blockDim.x + threadIdx.x) >> 5;
    if (gw >= NN) return;
    int lane = threadIdx.x & 31;
    const float4* h4 = (const float4*)g_h1;
    float di = g_dinv[gw];
    float4 own = h4[gw * 32 + lane];
    float ax = di * own.x, ay = di * own.y, az = di * own.z, aw = di * own.w;
    int e = g_rowptr[gw], end = g_rowptr[gw + 1];
    for (; e + 1 < end; e += 2) {
        int s0 = g_srcs[e];
        int s1 = g_srcs[e + 1];
        float c0 = g_dinv[s0];
        float c1 = g_dinv[s1];
        float4 v0 = h4[s0 * 32 + lane];
        float4 v1 = h4[s1 * 32 + lane];
        ax = fmaf(c0, v0.x, ax);  ay = fmaf(c0, v0.y, ay);
        az = fmaf(c0, v0.z, az);  aw = fmaf(c0, v0.w, aw);
        ax = fmaf(c1, v1.x, ax);  ay = fmaf(c1, v1.y, ay);
        az = fmaf(c1, v1.z, az);  aw = fmaf(c1, v1.w, aw);
    }
    if (e < end) {
        int s = g_srcs[e];
        float c = g_dinv[s];
        float4 v = h4[s * 32 + lane];
        ax = fmaf(c, v.x, ax);  ay = fmaf(c, v.y, ay);
        az = fmaf(c, v.z, az);  aw = fmaf(c, v.w, aw);
    }
    float4 b = ((const float4*)bias)[lane];
    float ox = fmaxf(fmaf(di, ax, b.x), 0.f);
    float oy = fmaxf(fmaf(di, ay, b.y), 0.f);
    float oz = fmaxf(fmaf(di, az, b.z), 0.f);
    float ow = fmaxf(fmaf(di, aw, b.w), 0.f);
    unsigned h0 = 0, l0 = 0, h1 = 0, l1 = 0;
    split2(ox, h0, l0, 0);  split2(oy, h0, l0, 16);
    split2(oz, h1, l1, 0);  split2(ow, h1, l1, 16);
    ((uint2*)g_hhi)[(size_t)gw * 32 + lane] = make_uint2(h0, h1);
    ((uint2*)g_hlo)[(size_t)gw * 32 + lane] = make_uint2(l0, l1);
}

// ---------------- fused agg layer 2 + final (logits + log_softmax) ----------------
__global__ void __launch_bounds__(256) k_aggfinal(const float* __restrict__ bias,
                                                 const float* __restrict__ Wf,
                                                 const float* __restrict__ bf,
                                                 float* __restrict__ out) {
    __shared__ float WfT[128 * 40];
    __shared__ float bfs[40];
    __shared__ __align__(16) float hs[8][128];
    int t = threadIdx.x;
    for (int e = t; e < NCLS * 128; e += 256) {
        int c = e >> 7, k = e & 127;
        WfT[k * 40 + c] = Wf[e];
    }
    if (t < NCLS) bfs[t] = bf[t];
    __syncthreads();

    int w = t >> 5, lane = t & 31;
    const float4* h4 = (const float4*)g_h1;
    float4 b = ((const float4*)bias)[lane];

    for (int node = blockIdx.x * 8 + w; node < NN; node += gridDim.x * 8) {
        float di = g_dinv[node];
        float4 own = h4[node * 32 + lane];
        float ax = di * own.x, ay = di * own.y, az = di * own.z, aw = di * own.w;
        int e = g_rowptr[node], end = g_rowptr[node + 1];
        for (; e + 1 < end; e += 2) {
            int s0 = g_srcs[e];
            int s1 = g_srcs[e + 1];
            float c0 = g_dinv[s0];
            float c1 = g_dinv[s1];
            float4 v0 = h4[s0 * 32 + lane];
            float4 v1 = h4[s1 * 32 + lane];
            ax = fmaf(c0, v0.x, ax);  ay = fmaf(c0, v0.y, ay);
            az = fmaf(c0, v0.z, az);  aw = fmaf(c0, v0.w, aw);
            ax = fmaf(c1, v1.x, ax);  ay = fmaf(c1, v1.y, ay);
            az = fmaf(c1, v1.z, az);  aw = fmaf(c1, v1.w, aw);
        }
        if (e < end) {
            int s = g_srcs[e];
            float c = g_dinv[s];
            float4 v = h4[s * 32 + lane];
            ax = fmaf(c, v.x, ax);  ay = fmaf(c, v.y, ay);
            az = fmaf(c, v.z, az);  aw = fmaf(c, v.w, aw);
        }
        float4 o;
        o.x = fmaxf(fmaf(di, ax, b.x), 0.f);
        o.y = fmaxf(fmaf(di, ay, b.y), 0.f);
        o.z = fmaxf(fmaf(di, az, b.z), 0.f);
        o.w = fmaxf(fmaf(di, aw, b.w), 0.f);
        ((float4*)hs[w])[lane] = o;
        __syncwarp();

        float acc0 = bfs[lane];
        float acc1 = (lane < 8) ? bfs[32 + lane] : 0.f;
        #pragma unroll 4
        for (int k = 0; k < 128; k++) {
            float hk = hs[w][k];
            acc0 = fmaf(hk, WfT[k * 40 + lane], acc0);
            if (lane < 8) acc1 = fmaf(hk, WfT[k * 40 + 32 + lane], acc1);
        }
        float m = acc0;
        if (lane < 8) m = fmaxf(m, acc1);
        #pragma unroll
        for (int off = 16; off; off >>= 1)
            m = fmaxf(m, __shfl_xor_sync(0xffffffffu, m, off));
        float s = __expf(acc0 - m) + ((lane < 8) ? __expf(acc1 - m) : 0.f);
        #pragma unroll
        for (int off = 16; off; off >>= 1)
            s += __shfl_xor_sync(0xffffffffu, s, off);
        float lse = m + __logf(s);
        out[(size_t)node * 40 + lane] = acc0 - lse;
        if (lane < 8) out[(size_t)node * 40 + 32 + lane] = acc1 - lse;
        __syncwarp();
    }
}

// ---------------- launch ----------------
extern "C" void kernel_launch(void* const* d_in, const int* in_sizes, int n_in,
                              void* d_out, int out_size) {
    const float* x  = (const float*)d_in[0];
    const int*   ei = (const int*)d_in[1];
    const float* W1 = (const float*)d_in[2];
    const float* b1 = (const float*)d_in[3];
    const float* W2 = (const float*)d_in[4];
    const float* b2 = (const float*)d_in[5];
    const float* Wf = (const float*)d_in[6];
    const float* bf = (const float*)d_in[7];
    float* out = (float*)d_out;

    const int* row = ei;        // sources
    const int* col = ei + EE;   // targets

    cudaFuncSetAttribute(k_mmagemm, cudaFuncAttributeMaxDynamicSharedMemorySize, SM_BYTES);
    int ablocks = (NN * 32 + 255) / 256;

    // ncu captures launch #4 -> GEMM1 there
    k_splitW<<<64, 256>>>(W1, W2);                               // 1
    k_zero<<<(NN + 255) / 256, 256>>>();                         // 2
    k_hist<<<(EE + 255) / 256, 256>>>(col);                      // 3
    k_mmagemm<<<GEMM_GRID, 256, SM_BYTES>>>(x, 0, NN);           // 4 <- profiled
    k_scan1<<<SCAN_NB, SCAN_BLK>>>();                            // 5
    k_scan2<<<1, SCAN_BLK>>>();                                  // 6
    k_scan3<<<SCAN_NB, SCAN_BLK>>>();                            // 7
    k_scatter<<<(EE + 255) / 256, 256>>>(row, col);              // 8
    k_agg1<<<ablocks, 256>>>(b1);                                // 9   -> g_hhi/g_hlo
    k_mmagemm<<<GEMM_GRID, 256, SM_BYTES>>>(x, 1, NN);           // 10
    k_aggfinal<<<1184, 256>>>(b2, Wf, bf, out);                  // 11
}

// round 16
// speedup vs baseline: 1.1254x; 1.0190x over previous
#include <cuda_runtime.h>
#include <cuda_bf16.h>
#include <cstdint>

#define NN 50000
#define EE 600000
#define DIM 128
#define NCLS 40
#define SCAN_BLK 256
#define SCAN_NB ((NN + SCAN_BLK - 1) / SCAN_BLK)   // 196
#define NTILES ((NN + 63) / 64)                    // 782
#define GEMM_GRID 444                              // 222 CTAs per N-half

// ---------------- scratch (static __device__, no allocation) ----------------
__device__ int   g_cnt[NN];
__device__ int   g_rowptr[NN + 1];
__device__ int   g_fill[NN];
__device__ int   g_srcs[EE];
__device__ int   g_bsum[SCAN_NB];
__device__ int   g_boff[SCAN_NB];
__device__ float g_dinv[NN];
__device__ __align__(16) float g_h1[(size_t)NN * DIM];     // GEMM out (fp32)
__device__ __align__(16) float g_h2[(size_t)NN * DIM];     // agg1 out (fp32, GEMM2 input)
__device__ __align__(16) uint32_t g_whi[2 * 8192];         // split W: [layer][n*64 + kpair]
__device__ __align__(16) uint32_t g_wlo[2 * 8192];

__device__ __forceinline__ void split2(float a, unsigned& hi, unsigned& lo, int sh) {
    __nv_bfloat16 hb = __float2bfloat16(a);
    float hf = __bfloat162float(hb);
    __nv_bfloat16 lb = __float2bfloat16(a - hf);
    hi |= (unsigned)__bfloat16_as_ushort(hb) << sh;
    lo |= (unsigned)__bfloat16_as_ushort(lb) << sh;
}

// ---------------- preprocessing ----------------
__global__ void k_zero() {
    int i = blockIdx.x * blockDim.x + threadIdx.x;
    if (i < NN) g_cnt[i] = 0;
}

__global__ void k_hist(const int* __restrict__ col) {
    int i = blockIdx.x * blockDim.x + threadIdx.x;
    if (i < EE) {
        unsigned c = (unsigned)col[i];
        if (c < NN) atomicAdd(&g_cnt[c], 1);
    }
}

__global__ void __launch_bounds__(SCAN_BLK) k_scan1() {
    __shared__ int ws[8];
    int t = threadIdx.x, lane = t & 31, w = t >> 5;
    int i = blockIdx.x * SCAN_BLK + t;
    int v = (i < NN) ? g_cnt[i] : 0;
    if (i < NN) g_dinv[i] = rsqrtf((float)v + 1.0f);
    int incl = v;
    #pragma unroll
    for (int off = 1; off < 32; off <<= 1) {
        int u = __shfl_up_sync(0xffffffffu, incl, off);
        if (lane >= off) incl += u;
    }
    if (lane == 31) ws[w] = incl;
    __syncthreads();
    if (w == 0 && lane < 8) {
        int s = ws[lane];
        #pragma unroll
        for (int off = 1; off < 8; off <<= 1) {
            int u = __shfl_up_sync(0xffu, s, off);
            if (lane >= off) s += u;
        }
        ws[lane] = s;
    }
    __syncthreads();
    int excl = incl - v + (w ? ws[w - 1] : 0);
    if (i < NN) g_rowptr[i] = excl;
    if (t == 0) g_bsum[blockIdx.x] = ws[7];
}

__global__ void __launch_bounds__(SCAN_BLK) k_scan2() {
    __shared__ int ws[8];
    int t = threadIdx.x, lane = t & 31, w = t >> 5;
    int v = (t < SCAN_NB) ? g_bsum[t] : 0;
    int incl = v;
    #pragma unroll
    for (int off = 1; off < 32; off <<= 1) {
        int u = __shfl_up_sync(0xffffffffu, incl, off);
        if (lane >= off) incl += u;
    }
    if (lane == 31) ws[w] = incl;
    __syncthreads();
    if (w == 0 && lane < 8) {
        int s = ws[lane];
        #pragma unroll
        for (int off = 1; off < 8; off <<= 1) {
            int u = __shfl_up_sync(0xffu, s, off);
            if (lane >= off) s += u;
        }
        ws[lane] = s;
    }
    __syncthreads();
    int excl = incl - v + (w ? ws[w - 1] : 0);
    if (t < SCAN_NB) g_boff[t] = excl;
    if (t == SCAN_NB - 1) g_rowptr[NN] = excl + v;
}

__global__ void __launch_bounds__(SCAN_BLK) k_scan3() {
    int i = blockIdx.x * SCAN_BLK + threadIdx.x;
    if (i < NN) {
        int e = g_rowptr[i] + g_boff[blockIdx.x];
        g_rowptr[i] = e;
        g_fill[i] = e;
    }
}

__global__ void k_scatter(const int* __restrict__ row,
                          const int* __restrict__ col) {
    int i = blockIdx.x * blockDim.x + threadIdx.x;
    if (i < EE) {
        unsigned c = (unsigned)col[i];
        unsigned r = (unsigned)row[i];
        if (c < NN && r < NN) {
            int p = atomicAdd(&g_fill[c], 1);
            g_srcs[p] = (int)r;
        }
    }
}

// ---------------- weight splitting ----------------
// g_whi layout: [layer][n*64 + kpair], word = bf16(k=2kp) | bf16(k=2kp+1)<<16
__global__ void k_splitW(const float* __restrict__ W1, const float* __restrict__ W2) {
    int i = blockIdx.x * blockDim.x + threadIdx.x;
    if (i >= 2 * 8192) return;
    const float* W = (i < 8192) ? W1 : W2;
    int j = i & 8191;                       // n*64 + kp
    int nn = j >> 6, kp = j & 63;
    float w0 = W[nn * 128 + 2 * kp];
    float w1 = W[nn * 128 + 2 * kp + 1];
    unsigned hi = 0, lo = 0;
    split2(w0, hi, lo, 0);
    split2(w1, hi, lo, 16);
    g_whi[i] = hi;
    g_wlo[i] = lo;
}

// ---------------- persistent N-split mma.sync GEMM via ldmatrix ----------------
// g_h1[n,128] = A[n,128] @ W[128,128]^T ; split-bf16 3-term, fp32 accumulate.
// A always fp32 (x for layer0, g_h2 for layer1), split inline during fill.
#define PADW 68
#define SA_LO_W (64 * PADW)                // 4352
#define SB_HI_W (2 * 64 * PADW)            // 8704
#define SB_LO_W (SB_HI_W + 64 * PADW)      // 13056
#define SMW_TOT (SB_LO_W + 64 * PADW)      // 17408 words
#define SM_BYTES (SMW_TOT * 4)             // 69632

__device__ __forceinline__ void mma_bf16(float* d, const unsigned* a, unsigned b0, unsigned b1) {
    asm volatile(
        "mma.sync.aligned.m16n8k16.row.col.f32.bf16.bf16.f32 "
        "{%0,%1,%2,%3}, {%4,%5,%6,%7}, {%8,%9}, {%0,%1,%2,%3};"
        : "+f"(d[0]), "+f"(d[1]), "+f"(d[2]), "+f"(d[3])
        : "r"(a[0]), "r"(a[1]), "r"(a[2]), "r"(a[3]), "r"(b0), "r"(b1));
}

#define LDSM_X4(r0, r1, r2, r3, addr) \
    asm volatile("ldmatrix.sync.aligned.m8n8.x4.shared.b16 {%0,%1,%2,%3}, [%4];" \
        : "=r"(r0), "=r"(r1), "=r"(r2), "=r"(r3) : "r"(addr))

__device__ __forceinline__ uint32_t smem_u32(const void* p) {
    uint32_t a;
    asm("{ .reg .u64 t; cvta.to.shared.u64 t, %1; cvt.u32.u64 %0, t; }" : "=r"(a) : "l"(p));
    return a;
}

__global__ void __launch_bounds__(256, 3)
k_mmagemm(const float* __restrict__ x, int layer, int n) {
    extern __shared__ __align__(16) uint32_t smw[];
    uint32_t* SAh = smw;
    uint32_t* SAl = smw + SA_LO_W;
    uint32_t* SBh = smw + SB_HI_W;
    uint32_t* SBl = smw + SB_LO_W;
    int t = threadIdx.x, wid = t >> 5, lane = t & 31;
    int halfN = blockIdx.x & 1;
    int cta   = blockIdx.x >> 1;
    int ctas  = gridDim.x >> 1;

    const float4* A4 = (const float4*)(layer ? (const float*)g_h2 : x);

    // ---- B-half fill ONCE: rows [halfN*64, +64), 4096 words per buffer ----
    {
        const uint4* W4h = (const uint4*)(g_whi + layer * 8192 + halfN * 64 * 64);
        const uint4* W4l = (const uint4*)(g_wlo + layer * 8192 + halfN * 64 * 64);
        #pragma unroll
        for (int p = 0; p < 4; p++) {
            int i4 = t + p * 256;
            int w = i4 * 4;
            int nr = w >> 6, wc = w & 63;
            uint4 vh = W4h[i4];
            uint4 vl = W4l[i4];
            int so = nr * PADW + wc;
            *(uint4*)(SBh + so) = vh;
            *(uint4*)(SBl + so) = vl;
        }
    }

    // compute-lane constants
    int grp = lane >> 2, tig = lane & 3;
    int rowg = wid & 3, colg = wid >> 2;
    int lr = lane & 7, lg = lane >> 3;
    int rsel = (lg & 1) << 3;
    int csel = (lg >> 1) << 2;
    uint32_t smb = smem_u32(smw);
    uint32_t aHb = smb + (uint32_t)(((rowg * 16 + lr + rsel) * PADW + csel) * 4);
    uint32_t aLb = aHb + SA_LO_W * 4;
    uint32_t bH = smb + (uint32_t)((SB_HI_W + (colg * 32 + lr + rsel) * PADW + csel) * 4);
    const uint32_t bLd = (SB_LO_W - SB_HI_W) * 4;
    const uint32_t pstep = 16 * PADW * 4;

    for (int tile = cta; tile < NTILES; tile += ctas) {
        int row0 = tile * 64;
        __syncthreads();   // prior compute done reading SA (first pass: orders B too)

        // ---- A tile fill: fp32 -> inline split ----
        #pragma unroll
        for (int p = 0; p < 8; p++) {
            int i2 = t + p * 256;
            int r = i2 >> 5, c2 = i2 & 31;
            int gr = row0 + r;
            if (gr >= n) gr = n - 1;
            float4 a = A4[(size_t)gr * 32 + c2];
            unsigned h0 = 0, l0 = 0, h1 = 0, l1 = 0;
            split2(a.x, h0, l0, 0);  split2(a.y, h0, l0, 16);
            split2(a.z, h1, l1, 0);  split2(a.w, h1, l1, 16);
            int so = r * PADW + c2 * 2;
            SAh[so] = h0;  SAh[so + 1] = h1;
            SAl[so] = l0;  SAl[so + 1] = l1;
        }
        __syncthreads();   // A ready

        float acc[4][4];
        #pragma unroll
        for (int i = 0; i < 4; i++)
            #pragma unroll
            for (int j = 0; j < 4; j++) acc[i][j] = 0.f;

        #pragma unroll
        for (int ks = 0; ks < 8; ks++) {
            uint32_t kadd = ks * 32;
            unsigned ah[4], al[4];
            LDSM_X4(ah[0], ah[1], ah[2], ah[3], aHb + kadd);
            LDSM_X4(al[0], al[1], al[2], al[3], aLb + kadd);
            #pragma unroll
            for (int p = 0; p < 2; p++) {
                unsigned bh[4], bl[4];
                uint32_t ba = bH + p * pstep + kadd;
                LDSM_X4(bh[0], bh[1], bh[2], bh[3], ba);
                LDSM_X4(bl[0], bl[1], bl[2], bl[3], ba + bLd);
                mma_bf16(acc[2 * p],     ah, bh[0], bh[2]);
                mma_bf16(acc[2 * p],     ah, bl[0], bl[2]);
                mma_bf16(acc[2 * p],     al, bh[0], bh[2]);
                mma_bf16(acc[2 * p + 1], ah, bh[1], bh[3]);
                mma_bf16(acc[2 * p + 1], ah, bl[1], bl[3]);
                mma_bf16(acc[2 * p + 1], al, bh[1], bh[3]);
            }
        }

        int gr0 = row0 + rowg * 16 + grp;
        int gr1 = gr0 + 8;
        #pragma unroll
        for (int j = 0; j < 4; j++) {
            int cc = halfN * 64 + colg * 32 + (j >> 1) * 16 + (j & 1) * 8 + 2 * tig;
            if (gr0 < n) *(float2*)(g_h1 + (size_t)gr0 * 128 + cc) = make_float2(acc[j][0], acc[j][1]);
            if (gr1 < n) *(float2*)(g_h1 + (size_t)gr1 * 128 + cc) = make_float2(acc[j][2], acc[j][3]);
        }
    }
}

// ---------------- agg layer 1: gather + bias + relu -> fp32 g_h2 ----------------
__global__ void __launch_bounds__(256) k_agg1(const float* __restrict__ bias) {
    int gw = (blockIdx.x * blockDim.x + threadIdx.x) >> 5;
    if (gw >= NN) return;
    int lane = threadIdx.x & 31;
    const float4* h4 = (const float4*)g_h1;
    float di = g_dinv[gw];
    float4 own = h4[gw * 32 + lane];
    float ax = di * own.x, ay = di * own.y, az = di * own.z, aw = di * own.w;
    int e = g_rowptr[gw], end = g_rowptr[gw + 1];
    for (; e + 1 < end; e += 2) {
        int s0 = g_srcs[e];
        int s1 = g_srcs[e + 1];
        float c0 = g_dinv[s0];
        float c1 = g_dinv[s1];
        float4 v0 = h4[s0 * 32 + lane];
        float4 v1 = h4[s1 * 32 + lane];
        ax = fmaf(c0, v0.x, ax);  ay = fmaf(c0, v0.y, ay);
        az = fmaf(c0, v0.z, az);  aw = fmaf(c0, v0.w, aw);
        ax = fmaf(c1, v1.x, ax);  ay = fmaf(c1, v1.y, ay);
        az = fmaf(c1, v1.z, az);  aw = fmaf(c1, v1.w, aw);
    }
    if (e < end) {
        int s = g_srcs[e];
        float c = g_dinv[s];
        float4 v = h4[s * 32 + lane];
        ax = fmaf(c, v.x, ax);  ay = fmaf(c, v.y, ay);
        az = fmaf(c, v.z, az);  aw = fmaf(c, v.w, aw);
    }
    float4 b = ((const float4*)bias)[lane];
    float4 o;
    o.x = fmaxf(fmaf(di, ax, b.x), 0.f);
    o.y = fmaxf(fmaf(di, ay, b.y), 0.f);
    o.z = fmaxf(fmaf(di, az, b.z), 0.f);
    o.w = fmaxf(fmaf(di, aw, b.w), 0.f);
    ((float4*)g_h2)[gw * 32 + lane] = o;
}

// ---------------- fused agg layer 2 + final (logits + log_softmax) ----------------
__global__ void __launch_bounds__(256) k_aggfinal(const float* __restrict__ bias,
                                                 const float* __restrict__ Wf,
                                                 const float* __restrict__ bf,
                                                 float* __restrict__ out) {
    __shared__ float WfT[128 * 40];
    __shared__ float bfs[40];
    __shared__ __align__(16) float hs[8][128];
    int t = threadIdx.x;
    for (int e = t; e < NCLS * 128; e += 256) {
        int c = e >> 7, k = e & 127;
        WfT[k * 40 + c] = Wf[e];
    }
    if (t < NCLS) bfs[t] = bf[t];
    __syncthreads();

    int w = t >> 5, lane = t & 31;
    const float4* h4 = (const float4*)g_h1;
    float4 b = ((const float4*)bias)[lane];

    for (int node = blockIdx.x * 8 + w; node < NN; node += gridDim.x * 8) {
        float di = g_dinv[node];
        float4 own = h4[node * 32 + lane];
        float ax = di * own.x, ay = di * own.y, az = di * own.z, aw = di * own.w;
        int e = g_rowptr[node], end = g_rowptr[node + 1];
        for (; e + 1 < end; e += 2) {
            int s0 = g_srcs[e];
            int s1 = g_srcs[e + 1];
            float c0 = g_dinv[s0];
            float c1 = g_dinv[s1];
            float4 v0 = h4[s0 * 32 + lane];
            float4 v1 = h4[s1 * 32 + lane];
            ax = fmaf(c0, v0.x, ax);  ay = fmaf(c0, v0.y, ay);
            az = fmaf(c0, v0.z, az);  aw = fmaf(c0, v0.w, aw);
            ax = fmaf(c1, v1.x, ax);  ay = fmaf(c1, v1.y, ay);
            az = fmaf(c1, v1.z, az);  aw = fmaf(c1, v1.w, aw);
        }
        if (e < end) {
            int s = g_srcs[e];
            float c = g_dinv[s];
            float4 v = h4[s * 32 + lane];
            ax = fmaf(c, v.x, ax);  ay = fmaf(c, v.y, ay);
            az = fmaf(c, v.z, az);  aw = fmaf(c, v.w, aw);
        }
        float4 o;
        o.x = fmaxf(fmaf(di, ax, b.x), 0.f);
        o.y = fmaxf(fmaf(di, ay, b.y), 0.f);
        o.z = fmaxf(fmaf(di, az, b.z), 0.f);
        o.w = fmaxf(fmaf(di, aw, b.w), 0.f);
        ((float4*)hs[w])[lane] = o;
        __syncwarp();

        float acc0 = bfs[lane];
        float acc1 = (lane < 8) ? bfs[32 + lane] : 0.f;
        #pragma unroll 4
        for (int k = 0; k < 128; k++) {
            float hk = hs[w][k];
            acc0 = fmaf(hk, WfT[k * 40 + lane], acc0);
            if (lane < 8) acc1 = fmaf(hk, WfT[k * 40 + 32 + lane], acc1);
        }
        float m = acc0;
        if (lane < 8) m = fmaxf(m, acc1);
        #pragma unroll
        for (int off = 16; off; off >>= 1)
            m = fmaxf(m, __shfl_xor_sync(0xffffffffu, m, off));
        float s = __expf(acc0 - m) + ((lane < 8) ? __expf(acc1 - m) : 0.f);
        #pragma unroll
        for (int off = 16; off; off >>= 1)
            s += __shfl_xor_sync(0xffffffffu, s, off);
        float lse = m + __logf(s);
        out[(size_t)node * 40 + lane] = acc0 - lse;
        if (lane < 8) out[(size_t)node * 40 + 32 + lane] = acc1 - lse;
        __syncwarp();
    }
}

// ---------------- launch ----------------
static cudaStream_t g_s2 = nullptr;
static cudaEvent_t  g_evF = nullptr, g_evJ = nullptr;

extern "C" void kernel_launch(void* const* d_in, const int* in_sizes, int n_in,
                              void* d_out, int out_size) {
    const float* x  = (const float*)d_in[0];
    const int*   ei = (const int*)d_in[1];
    const float* W1 = (const float*)d_in[2];
    const float* b1 = (const float*)d_in[3];
    const float* W2 = (const float*)d_in[4];
    const float* b2 = (const float*)d_in[5];
    const float* Wf = (const float*)d_in[6];
    const float* bf = (const float*)d_in[7];
    float* out = (float*)d_out;

    const int* row = ei;        // sources
    const int* col = ei + EE;   // targets

    // one-time infra setup (first call is the non-capturing correctness run)
    if (!g_evJ) {
        if (cudaStreamCreateWithFlags(&g_s2, cudaStreamNonBlocking) != cudaSuccess) g_s2 = nullptr;
        cudaEventCreateWithFlags(&g_evF, cudaEventDisableTiming);
        cudaEventCreateWithFlags(&g_evJ, cudaEventDisableTiming);
        cudaFuncSetAttribute(k_mmagemm, cudaFuncAttributeMaxDynamicSharedMemorySize, SM_BYTES);
    }
    cudaStream_t s2 = g_s2 ? g_s2 : (cudaStream_t)0;

    int ablocks = (NN * 32 + 255) / 256;

    // fork: preprocessing (s2) runs concurrently with splitW + GEMM1 (default)
    cudaEventRecord(g_evF, 0);
    cudaStreamWaitEvent(s2, g_evF, 0);

    k_splitW<<<64, 256>>>(W1, W2);                                   // default
    k_mmagemm<<<GEMM_GRID, 256, SM_BYTES>>>(x, 0, NN);               // default: x@W1^T -> g_h1

    k_zero<<<(NN + 255) / 256, 256, 0, s2>>>();                      // s2
    k_hist<<<(EE + 255) / 256, 256, 0, s2>>>(col);                   // s2
    k_scan1<<<SCAN_NB, SCAN_BLK, 0, s2>>>();                         // s2
    k_scan2<<<1, SCAN_BLK, 0, s2>>>();                               // s2
    k_scan3<<<SCAN_NB, SCAN_BLK, 0, s2>>>();                         // s2
    k_scatter<<<(EE + 255) / 256, 256, 0, s2>>>(row, col);           // s2

    cudaEventRecord(g_evJ, s2);
    cudaStreamWaitEvent(0, g_evJ, 0);

    // join: rest on default stream
    k_agg1<<<ablocks, 256>>>(b1);                                    // g_h1 -> g_h2 (fp32)
    k_mmagemm<<<GEMM_GRID, 256, SM_BYTES>>>(x, 1, NN);               // g_h2@W2^T -> g_h1
    k_aggfinal<<<1184, 256>>>(b2, Wf, bf, out);                      // -> out
}

// round 17
// speedup vs baseline: 1.1956x; 1.0624x over previous
#include <cuda_runtime.h>
#include <cuda_bf16.h>
#include <cstdint>

#define NN 50000
#define EE 600000
#define DIM 128
#define NCLS 40
#define SCAN_BLK 256
#define SCAN_NB ((NN + SCAN_BLK - 1) / SCAN_BLK)   // 196
#define NTILES ((NN + 63) / 64)                    // 782
#define GEMM_GRID 444                              // 222 CTAs per N-half

// ---------------- scratch (static __device__, no allocation) ----------------
__device__ int   g_cnt[NN];
__device__ int   g_rowptr[NN + 1];
__device__ int   g_fill[NN];
__device__ int   g_srcs[EE];
__device__ int   g_bsum[SCAN_NB];
__device__ int   g_boff[SCAN_NB];
__device__ float g_dinv[NN];
__device__ __align__(16) uint32_t g_h1b[(size_t)NN * 64];  // GEMM out, packed bf16x2
__device__ __align__(16) float g_h2[(size_t)NN * DIM];     // agg1 out (fp32, GEMM2 input)
__device__ __align__(16) uint32_t g_whi[2 * 8192];         // split W: [layer][n*64 + kpair]
__device__ __align__(16) uint32_t g_wlo[2 * 8192];

__device__ __forceinline__ void split2(float a, unsigned& hi, unsigned& lo, int sh) {
    __nv_bfloat16 hb = __float2bfloat16(a);
    float hf = __bfloat162float(hb);
    __nv_bfloat16 lb = __float2bfloat16(a - hf);
    hi |= (unsigned)__bfloat16_as_ushort(hb) << sh;
    lo |= (unsigned)__bfloat16_as_ushort(lb) << sh;
}

// pack two fp32 into bf16x2 word: low half = a, high half = b
__device__ __forceinline__ uint32_t pack_bf2(float a, float b) {
    uint32_t r;
    asm("cvt.rn.bf16x2.f32 %0, %1, %2;" : "=r"(r) : "f"(b), "f"(a));
    return r;
}
// unpack: x = low half, y = high half
__device__ __forceinline__ float2 unpack_bf2(uint32_t u) {
    float2 r;
    r.x = __uint_as_float(u << 16);
    r.y = __uint_as_float(u & 0xffff0000u);
    return r;
}

// ---------------- preprocessing ----------------
__global__ void k_zero() {
    int i = blockIdx.x * blockDim.x + threadIdx.x;
    if (i < NN) g_cnt[i] = 0;
}

__global__ void k_hist(const int* __restrict__ col) {
    int i = blockIdx.x * blockDim.x + threadIdx.x;
    if (i < EE) {
        unsigned c = (unsigned)col[i];
        if (c < NN) atomicAdd(&g_cnt[c], 1);
    }
}

__global__ void __launch_bounds__(SCAN_BLK) k_scan1() {
    __shared__ int ws[8];
    int t = threadIdx.x, lane = t & 31, w = t >> 5;
    int i = blockIdx.x * SCAN_BLK + t;
    int v = (i < NN) ? g_cnt[i] : 0;
    if (i < NN) g_dinv[i] = rsqrtf((float)v + 1.0f);
    int incl = v;
    #pragma unroll
    for (int off = 1; off < 32; off <<= 1) {
        int u = __shfl_up_sync(0xffffffffu, incl, off);
        if (lane >= off) incl += u;
    }
    if (lane == 31) ws[w] = incl;
    __syncthreads();
    if (w == 0 && lane < 8) {
        int s = ws[lane];
        #pragma unroll
        for (int off = 1; off < 8; off <<= 1) {
            int u = __shfl_up_sync(0xffu, s, off);
            if (lane >= off) s += u;
        }
        ws[lane] = s;
    }
    __syncthreads();
    int excl = incl - v + (w ? ws[w - 1] : 0);
    if (i < NN) g_rowptr[i] = excl;
    if (t == 0) g_bsum[blockIdx.x] = ws[7];
}

__global__ void __launch_bounds__(SCAN_BLK) k_scan2() {
    __shared__ int ws[8];
    int t = threadIdx.x, lane = t & 31, w = t >> 5;
    int v = (t < SCAN_NB) ? g_bsum[t] : 0;
    int incl = v;
    #pragma unroll
    for (int off = 1; off < 32; off <<= 1) {
        int u = __shfl_up_sync(0xffffffffu, incl, off);
        if (lane >= off) incl += u;
    }
    if (lane == 31) ws[w] = incl;
    __syncthreads();
    if (w == 0 && lane < 8) {
        int s = ws[lane];
        #pragma unroll
        for (int off = 1; off < 8; off <<= 1) {
            int u = __shfl_up_sync(0xffu, s, off);
            if (lane >= off) s += u;
        }
        ws[lane] = s;
    }
    __syncthreads();
    int excl = incl - v + (w ? ws[w - 1] : 0);
    if (t < SCAN_NB) g_boff[t] = excl;
    if (t == SCAN_NB - 1) g_rowptr[NN] = excl + v;
}

__global__ void __launch_bounds__(SCAN_BLK) k_scan3() {
    int i = blockIdx.x * SCAN_BLK + threadIdx.x;
    if (i < NN) {
        int e = g_rowptr[i] + g_boff[blockIdx.x];
        g_rowptr[i] = e;
        g_fill[i] = e;
    }
}

__global__ void k_scatter(const int* __restrict__ row,
                          const int* __restrict__ col) {
    int i = blockIdx.x * blockDim.x + threadIdx.x;
    if (i < EE) {
        unsigned c = (unsigned)col[i];
        unsigned r = (unsigned)row[i];
        if (c < NN && r < NN) {
            int p = atomicAdd(&g_fill[c], 1);
            g_srcs[p] = (int)r;
        }
    }
}

// ---------------- weight splitting ----------------
__global__ void k_splitW(const float* __restrict__ W1, const float* __restrict__ W2) {
    int i = blockIdx.x * blockDim.x + threadIdx.x;
    if (i >= 2 * 8192) return;
    const float* W = (i < 8192) ? W1 : W2;
    int j = i & 8191;                       // n*64 + kp
    int nn = j >> 6, kp = j & 63;
    float w0 = W[nn * 128 + 2 * kp];
    float w1 = W[nn * 128 + 2 * kp + 1];
    unsigned hi = 0, lo = 0;
    split2(w0, hi, lo, 0);
    split2(w1, hi, lo, 16);
    g_whi[i] = hi;
    g_wlo[i] = lo;
}

// ---------------- persistent N-split mma.sync GEMM via ldmatrix ----------------
// g_h1b[n,64words] = bf16x2( A[n,128] @ W[128,128]^T ); split-bf16 3-term, fp32 acc.
#define PADW 68
#define SA_LO_W (64 * PADW)                // 4352
#define SB_HI_W (2 * 64 * PADW)            // 8704
#define SB_LO_W (SB_HI_W + 64 * PADW)      // 13056
#define SMW_TOT (SB_LO_W + 64 * PADW)      // 17408 words
#define SM_BYTES (SMW_TOT * 4)             // 69632

__device__ __forceinline__ void mma_bf16(float* d, const unsigned* a, unsigned b0, unsigned b1) {
    asm volatile(
        "mma.sync.aligned.m16n8k16.row.col.f32.bf16.bf16.f32 "
        "{%0,%1,%2,%3}, {%4,%5,%6,%7}, {%8,%9}, {%0,%1,%2,%3};"
        : "+f"(d[0]), "+f"(d[1]), "+f"(d[2]), "+f"(d[3])
        : "r"(a[0]), "r"(a[1]), "r"(a[2]), "r"(a[3]), "r"(b0), "r"(b1));
}

#define LDSM_X4(r0, r1, r2, r3, addr) \
    asm volatile("ldmatrix.sync.aligned.m8n8.x4.shared.b16 {%0,%1,%2,%3}, [%4];" \
        : "=r"(r0), "=r"(r1), "=r"(r2), "=r"(r3) : "r"(addr))

__device__ __forceinline__ uint32_t smem_u32(const void* p) {
    uint32_t a;
    asm("{ .reg .u64 t; cvta.to.shared.u64 t, %1; cvt.u32.u64 %0, t; }" : "=r"(a) : "l"(p));
    return a;
}

__global__ void __launch_bounds__(256, 3)
k_mmagemm(const float* __restrict__ x, int layer, int n) {
    extern __shared__ __align__(16) uint32_t smw[];
    uint32_t* SAh = smw;
    uint32_t* SAl = smw + SA_LO_W;
    uint32_t* SBh = smw + SB_HI_W;
    uint32_t* SBl = smw + SB_LO_W;
    int t = threadIdx.x, wid = t >> 5, lane = t & 31;
    int halfN = blockIdx.x & 1;
    int cta   = blockIdx.x >> 1;
    int ctas  = gridDim.x >> 1;

    const float4* A4 = (const float4*)(layer ? (const float*)g_h2 : x);

    // ---- B-half fill ONCE ----
    {
        const uint4* W4h = (const uint4*)(g_whi + layer * 8192 + halfN * 64 * 64);
        const uint4* W4l = (const uint4*)(g_wlo + layer * 8192 + halfN * 64 * 64);
        #pragma unroll
        for (int p = 0; p < 4; p++) {
            int i4 = t + p * 256;
            int w = i4 * 4;
            int nr = w >> 6, wc = w & 63;
            uint4 vh = W4h[i4];
            uint4 vl = W4l[i4];
            int so = nr * PADW + wc;
            *(uint4*)(SBh + so) = vh;
            *(uint4*)(SBl + so) = vl;
        }
    }

    int grp = lane >> 2, tig = lane & 3;
    int rowg = wid & 3, colg = wid >> 2;
    int lr = lane & 7, lg = lane >> 3;
    int rsel = (lg & 1) << 3;
    int csel = (lg >> 1) << 2;
    uint32_t smb = smem_u32(smw);
    uint32_t aHb = smb + (uint32_t)(((rowg * 16 + lr + rsel) * PADW + csel) * 4);
    uint32_t aLb = aHb + SA_LO_W * 4;
    uint32_t bH = smb + (uint32_t)((SB_HI_W + (colg * 32 + lr + rsel) * PADW + csel) * 4);
    const uint32_t bLd = (SB_LO_W - SB_HI_W) * 4;
    const uint32_t pstep = 16 * PADW * 4;

    for (int tile = cta; tile < NTILES; tile += ctas) {
        int row0 = tile * 64;
        __syncthreads();

        // ---- A tile fill: fp32 -> inline split ----
        #pragma unroll
        for (int p = 0; p < 8; p++) {
            int i2 = t + p * 256;
            int r = i2 >> 5, c2 = i2 & 31;
            int gr = row0 + r;
            if (gr >= n) gr = n - 1;
            float4 a = A4[(size_t)gr * 32 + c2];
            unsigned h0 = 0, l0 = 0, h1 = 0, l1 = 0;
            split2(a.x, h0, l0, 0);  split2(a.y, h0, l0, 16);
            split2(a.z, h1, l1, 0);  split2(a.w, h1, l1, 16);
            int so = r * PADW + c2 * 2;
            SAh[so] = h0;  SAh[so + 1] = h1;
            SAl[so] = l0;  SAl[so + 1] = l1;
        }
        __syncthreads();

        float acc[4][4];
        #pragma unroll
        for (int i = 0; i < 4; i++)
            #pragma unroll
            for (int j = 0; j < 4; j++) acc[i][j] = 0.f;

        #pragma unroll
        for (int ks = 0; ks < 8; ks++) {
            uint32_t kadd = ks * 32;
            unsigned ah[4], al[4];
            LDSM_X4(ah[0], ah[1], ah[2], ah[3], aHb + kadd);
            LDSM_X4(al[0], al[1], al[2], al[3], aLb + kadd);
            #pragma unroll
            for (int p = 0; p < 2; p++) {
                unsigned bh[4], bl[4];
                uint32_t ba = bH + p * pstep + kadd;
                LDSM_X4(bh[0], bh[1], bh[2], bh[3], ba);
                LDSM_X4(bl[0], bl[1], bl[2], bl[3], ba + bLd);
                mma_bf16(acc[2 * p],     ah, bh[0], bh[2]);
                mma_bf16(acc[2 * p],     ah, bl[0], bl[2]);
                mma_bf16(acc[2 * p],     al, bh[0], bh[2]);
                mma_bf16(acc[2 * p + 1], ah, bh[1], bh[3]);
                mma_bf16(acc[2 * p + 1], ah, bl[1], bl[3]);
                mma_bf16(acc[2 * p + 1], al, bh[1], bh[3]);
            }
        }

        // ---- epilogue: pack fp32 pairs -> bf16x2 words ----
        int gr0 = row0 + rowg * 16 + grp;
        int gr1 = gr0 + 8;
        #pragma unroll
        for (int j = 0; j < 4; j++) {
            int cc = halfN * 64 + colg * 32 + (j >> 1) * 16 + (j & 1) * 8 + 2 * tig;
            if (gr0 < n) g_h1b[(size_t)gr0 * 64 + (cc >> 1)] = pack_bf2(acc[j][0], acc[j][1]);
            if (gr1 < n) g_h1b[(size_t)gr1 * 64 + (cc >> 1)] = pack_bf2(acc[j][2], acc[j][3]);
        }
    }
}

// ---------------- agg layer 1: bf16 gather + bias + relu -> fp32 g_h2 ----------------
__global__ void __launch_bounds__(256) k_agg1(const float* __restrict__ bias) {
    int gw = (blockIdx.x * blockDim.x + threadIdx.x) >> 5;
    if (gw >= NN) return;
    int lane = threadIdx.x & 31;
    const uint2* hb = (const uint2*)g_h1b;   // per node: 32 uint2 (4 bf16 values each)
    float di = g_dinv[gw];
    uint2 ov = hb[(size_t)gw * 32 + lane];
    float2 o0 = unpack_bf2(ov.x), o1 = unpack_bf2(ov.y);
    float ax = di * o0.x, ay = di * o0.y, az = di * o1.x, aw = di * o1.y;
    int e = g_rowptr[gw], end = g_rowptr[gw + 1];
    for (; e + 1 < end; e += 2) {
        int s0 = g_srcs[e];
        int s1 = g_srcs[e + 1];
        float c0 = g_dinv[s0];
        float c1 = g_dinv[s1];
        uint2 u0 = hb[(size_t)s0 * 32 + lane];
        uint2 u1 = hb[(size_t)s1 * 32 + lane];
        float2 v00 = unpack_bf2(u0.x), v01 = unpack_bf2(u0.y);
        float2 v10 = unpack_bf2(u1.x), v11 = unpack_bf2(u1.y);
        ax = fmaf(c0, v00.x, ax);  ay = fmaf(c0, v00.y, ay);
        az = fmaf(c0, v01.x, az);  aw = fmaf(c0, v01.y, aw);
        ax = fmaf(c1, v10.x, ax);  ay = fmaf(c1, v10.y, ay);
        az = fmaf(c1, v11.x, az);  aw = fmaf(c1, v11.y, aw);
    }
    if (e < end) {
        int s = g_srcs[e];
        float c = g_dinv[s];
        uint2 u = hb[(size_t)s * 32 + lane];
        float2 v0 = unpack_bf2(u.x), v1 = unpack_bf2(u.y);
        ax = fmaf(c, v0.x, ax);  ay = fmaf(c, v0.y, ay);
        az = fmaf(c, v1.x, az);  aw = fmaf(c, v1.y, aw);
    }
    float4 b = ((const float4*)bias)[lane];
    float4 o;
    o.x = fmaxf(fmaf(di, ax, b.x), 0.f);
    o.y = fmaxf(fmaf(di, ay, b.y), 0.f);
    o.z = fmaxf(fmaf(di, az, b.z), 0.f);
    o.w = fmaxf(fmaf(di, aw, b.w), 0.f);
    ((float4*)g_h2)[gw * 32 + lane] = o;
}

// ---------------- fused agg layer 2 + final (bf16 gather + logits + log_softmax) ----------------
__global__ void __launch_bounds__(256) k_aggfinal(const float* __restrict__ bias,
                                                 const float* __restrict__ Wf,
                                                 const float* __restrict__ bf,
                                                 float* __restrict__ out) {
    __shared__ float WfT[128 * 40];
    __shared__ float bfs[40];
    __shared__ __align__(16) float hs[8][128];
    int t = threadIdx.x;
    for (int e = t; e < NCLS * 128; e += 256) {
        int c = e >> 7, k = e & 127;
        WfT[k * 40 + c] = Wf[e];
    }
    if (t < NCLS) bfs[t] = bf[t];
    __syncthreads();

    int w = t >> 5, lane = t & 31;
    const uint2* hb = (const uint2*)g_h1b;
    float4 b = ((const float4*)bias)[lane];

    for (int node = blockIdx.x * 8 + w; node < NN; node += gridDim.x * 8) {
        float di = g_dinv[node];
        uint2 ov = hb[(size_t)node * 32 + lane];
        float2 o0 = unpack_bf2(ov.x), o1 = unpack_bf2(ov.y);
        float ax = di * o0.x, ay = di * o0.y, az = di * o1.x, aw = di * o1.y;
        int e = g_rowptr[node], end = g_rowptr[node + 1];
        for (; e + 1 < end; e += 2) {
            int s0 = g_srcs[e];
            int s1 = g_srcs[e + 1];
            float c0 = g_dinv[s0];
            float c1 = g_dinv[s1];
            uint2 u0 = hb[(size_t)s0 * 32 + lane];
            uint2 u1 = hb[(size_t)s1 * 32 + lane];
            float2 v00 = unpack_bf2(u0.x), v01 = unpack_bf2(u0.y);
            float2 v10 = unpack_bf2(u1.x), v11 = unpack_bf2(u1.y);
            ax = fmaf(c0, v00.x, ax);  ay = fmaf(c0, v00.y, ay);
            az = fmaf(c0, v01.x, az);  aw = fmaf(c0, v01.y, aw);
            ax = fmaf(c1, v10.x, ax);  ay = fmaf(c1, v10.y, ay);
            az = fmaf(c1, v11.x, az);  aw = fmaf(c1, v11.y, aw);
        }
        if (e < end) {
            int s = g_srcs[e];
            float c = g_dinv[s];
            uint2 u = hb[(size_t)s * 32 + lane];
            float2 v0 = unpack_bf2(u.x), v1 = unpack_bf2(u.y);
            ax = fmaf(c, v0.x, ax);  ay = fmaf(c, v0.y, ay);
            az = fmaf(c, v1.x, az);  aw = fmaf(c, v1.y, aw);
        }
        float4 o;
        o.x = fmaxf(fmaf(di, ax, b.x), 0.f);
        o.y = fmaxf(fmaf(di, ay, b.y), 0.f);
        o.z = fmaxf(fmaf(di, az, b.z), 0.f);
        o.w = fmaxf(fmaf(di, aw, b.w), 0.f);
        ((float4*)hs[w])[lane] = o;
        __syncwarp();

        float acc0 = bfs[lane];
        float acc1 = (lane < 8) ? bfs[32 + lane] : 0.f;
        #pragma unroll 4
        for (int k = 0; k < 128; k++) {
            float hk = hs[w][k];
            acc0 = fmaf(hk, WfT[k * 40 + lane], acc0);
            if (lane < 8) acc1 = fmaf(hk, WfT[k * 40 + 32 + lane], acc1);
        }
        float m = acc0;
        if (lane < 8) m = fmaxf(m, acc1);
        #pragma unroll
        for (int off = 16; off; off >>= 1)
            m = fmaxf(m, __shfl_xor_sync(0xffffffffu, m, off));
        float s = __expf(acc0 - m) + ((lane < 8) ? __expf(acc1 - m) : 0.f);
        #pragma unroll
        for (int off = 16; off; off >>= 1)
            s += __shfl_xor_sync(0xffffffffu, s, off);
        float lse = m + __logf(s);
        out[(size_t)node * 40 + lane] = acc0 - lse;
        if (lane < 8) out[(size_t)node * 40 + 32 + lane] = acc1 - lse;
        __syncwarp();
    }
}

// ---------------- launch ----------------
static cudaStream_t g_s2 = nullptr;
static cudaEvent_t  g_evF = nullptr, g_evJ = nullptr;

extern "C" void kernel_launch(void* const* d_in, const int* in_sizes, int n_in,
                              void* d_out, int out_size) {
    const float* x  = (const float*)d_in[0];
    const int*   ei = (const int*)d_in[1];
    const float* W1 = (const float*)d_in[2];
    const float* b1 = (const float*)d_in[3];
    const float* W2 = (const float*)d_in[4];
    const float* b2 = (const float*)d_in[5];
    const float* Wf = (const float*)d_in[6];
    const float* bf = (const float*)d_in[7];
    float* out = (float*)d_out;

    const int* row = ei;        // sources
    const int* col = ei + EE;   // targets

    if (!g_evJ) {
        if (cudaStreamCreateWithFlags(&g_s2, cudaStreamNonBlocking) != cudaSuccess) g_s2 = nullptr;
        cudaEventCreateWithFlags(&g_evF, cudaEventDisableTiming);
        cudaEventCreateWithFlags(&g_evJ, cudaEventDisableTiming);
        cudaFuncSetAttribute(k_mmagemm, cudaFuncAttributeMaxDynamicSharedMemorySize, SM_BYTES);
    }
    cudaStream_t s2 = g_s2 ? g_s2 : (cudaStream_t)0;

    int ablocks = (NN * 32 + 255) / 256;

    // fork: preprocessing (s2) concurrent with splitW + GEMM1 (default)
    cudaEventRecord(g_evF, 0);
    cudaStreamWaitEvent(s2, g_evF, 0);

    k_splitW<<<64, 256>>>(W1, W2);
    k_mmagemm<<<GEMM_GRID, 256, SM_BYTES>>>(x, 0, NN);           // x@W1^T -> g_h1b (bf16)

    k_zero<<<(NN + 255) / 256, 256, 0, s2>>>();
    k_hist<<<(EE + 255) / 256, 256, 0, s2>>>(col);
    k_scan1<<<SCAN_NB, SCAN_BLK, 0, s2>>>();
    k_scan2<<<1, SCAN_BLK, 0, s2>>>();
    k_scan3<<<SCAN_NB, SCAN_BLK, 0, s2>>>();
    k_scatter<<<(EE + 255) / 256, 256, 0, s2>>>(row, col);

    cudaEventRecord(g_evJ, s2);
    cudaStreamWaitEvent(0, g_evJ, 0);

    // join
    k_agg1<<<ablocks, 256>>>(b1);                                // g_h1b -> g_h2 (fp32)
    k_mmagemm<<<GEMM_GRID, 256, SM_BYTES>>>(x, 1, NN);           // g_h2@W2^T -> g_h1b (bf16)
    k_aggfinal<<<1184, 256>>>(b2, Wf, bf, out);                  // -> out
}